// round 9
// baseline (speedup 1.0000x reference)
#include <cuda_runtime.h>
#include <cuda_bf16.h>
#include <math.h>

#define BB 16
#define SSQ 256
#define TTQ 128
#define DDQ 512
#define VVQ 32000
#define LLQ 3
#define R2F 0.70710678118654752440f

// ---------------- scratch (single __device__ array, no allocs) ----------------
__device__ float g_scratch[25690112];

// ---------------- bf16 split-pair tensor-core batched GEMM ----------------
// Double-buffered SMEM pipeline; optional fused im2col for conv layers.
struct GemmP {
    const float* A; long long a_sm, a_sk, a_b;
    const float* Bm; long long b_sk, b_sn, b_b;   // conv: Bm = x [B, D, Slen], b_b = D*Slen
    float* C; long long c_row, c_b;
    const float* bias; int bias_per_m;
    int M, N, K, mode;           // mode: 0 plain, 1 enc-out (pad zero + combined), 2 (+emb)*R2
    const int* tokens;           // mode1 epilogue mask AND enc-conv input mask
    const float* emb; long long emb_b;
    float* C2;
    int conv;                    // 0 none, 1 enc conv (pad 1 + token mask), 2 dec conv (causal pad 2)
    int Slen;                    // conv: x row length
};

__device__ __forceinline__ unsigned f2tf(float x) {
    unsigned r;
    asm("cvt.rna.tf32.f32 %0, %1;" : "=r"(r) : "f"(x));
    return r;
}

__device__ __forceinline__ void cvt_pair(float x0, float x1, unsigned& hw, unsigned& lw) {
    __nv_bfloat162 h = __floats2bfloat162_rn(x0, x1);
    float2 hf = __bfloat1622float2(h);
    __nv_bfloat162 l = __floats2bfloat162_rn(x0 - hf.x, x1 - hf.y);
    hw = *reinterpret_cast<unsigned*>(&h);
    lw = *reinterpret_cast<unsigned*>(&l);
}

__device__ __forceinline__ void mma16(float* d, const unsigned* a, const unsigned* b) {
    asm volatile(
        "mma.sync.aligned.m16n8k16.row.col.f32.bf16.bf16.f32 "
        "{%0,%1,%2,%3}, {%4,%5,%6,%7}, {%8,%9}, {%0,%1,%2,%3};"
        : "+f"(d[0]), "+f"(d[1]), "+f"(d[2]), "+f"(d[3])
        : "r"(a[0]), "r"(a[1]), "r"(a[2]), "r"(a[3]), "r"(b[0]), "r"(b[1]));
}

__device__ __forceinline__ void mma8(float* d, const unsigned* a, const unsigned* b) {
    asm volatile(
        "mma.sync.aligned.m16n8k8.row.col.f32.tf32.tf32.f32 "
        "{%0,%1,%2,%3}, {%4,%5,%6,%7}, {%8,%9}, {%0,%1,%2,%3};"
        : "+f"(d[0]), "+f"(d[1]), "+f"(d[2]), "+f"(d[3])
        : "r"(a[0]), "r"(a[1]), "r"(a[2]), "r"(a[3]), "r"(b[0]), "r"(b[1]));
}

// ---- A tile loaders: 128(m) x 32(k) into 16 regs ----
__device__ __forceinline__ void load_tileA(const GemmP& p, long long base, int m0, int k0,
                                           int tid, float* r) {
    if (p.a_sk == 1) {
        int mm = tid >> 1, kb = (tid & 1) << 4;
        const float* q = p.A + base + (long long)(m0 + mm) * p.a_sm + k0 + kb;
#pragma unroll
        for (int u = 0; u < 4; u++) {
            float4 v = *(const float4*)(q + u * 4);
            r[u * 4 + 0] = v.x; r[u * 4 + 1] = v.y; r[u * 4 + 2] = v.z; r[u * 4 + 3] = v.w;
        }
    } else {
#pragma unroll
        for (int q = 0; q < 8; q++) {
            int j = tid + q * 256;
            int mm = j & 127, k2 = j >> 7;
            long long b2 = base + (long long)(m0 + mm) * p.a_sm;
            r[q * 2]     = p.A[b2 + (long long)(k0 + 2 * k2) * p.a_sk];
            r[q * 2 + 1] = p.A[b2 + (long long)(k0 + 2 * k2 + 1) * p.a_sk];
        }
    }
}

// ---- B tile loaders: 32(k) x 128(n) into 16 regs; conv = fused im2col gather ----
__device__ __forceinline__ void load_tileB(const GemmP& p, long long base, int bz, int n0,
                                           int k0, int tid, float* r) {
    if (p.conv) {
        int pad = (p.conv == 1) ? 1 : 2;
#pragma unroll
        for (int q = 0; q < 8; q++) {
            int j = tid + q * 256;
            int nn = j & 127, k2 = j >> 7;
#pragma unroll
            for (int e = 0; e < 2; e++) {
                int k = k0 + 2 * k2 + e;
                int ic = k / 3, kk = k - ic * 3;
                int s2 = n0 + nn + kk - pad;
                bool ok = (s2 >= 0) && (s2 < p.Slen);
                if (p.conv == 1) ok = ok && (p.tokens[bz * SSQ + s2] != 0);
                r[q * 2 + e] = ok ? p.Bm[base + (long long)ic * p.Slen + s2] : 0.f;
            }
        }
    } else if (p.b_sk == 1) {
        int nn = tid >> 1, kb = (tid & 1) << 4;
        const float* q = p.Bm + base + (long long)(n0 + nn) * p.b_sn + k0 + kb;
#pragma unroll
        for (int u = 0; u < 4; u++) {
            float4 v = *(const float4*)(q + u * 4);
            r[u * 4 + 0] = v.x; r[u * 4 + 1] = v.y; r[u * 4 + 2] = v.z; r[u * 4 + 3] = v.w;
        }
    } else {
#pragma unroll
        for (int q = 0; q < 8; q++) {
            int j = tid + q * 256;
            int nn = j & 127, k2 = j >> 7;
            long long b2 = base + (long long)(n0 + nn) * p.b_sn;
            r[q * 2]     = p.Bm[b2 + (long long)(k0 + 2 * k2) * p.b_sk];
            r[q * 2 + 1] = p.Bm[b2 + (long long)(k0 + 2 * k2 + 1) * p.b_sk];
        }
    }
}

__device__ __forceinline__ void sts_tile(unsigned (*H)[136], unsigned (*L)[136],
                                         bool contig, int tid, const float* r) {
    if (contig) {
        int mm = tid >> 1, kb2 = (tid & 1) << 3;
#pragma unroll
        for (int u = 0; u < 8; u++)
            cvt_pair(r[u * 2], r[u * 2 + 1], H[kb2 + u][mm], L[kb2 + u][mm]);
    } else {
#pragma unroll
        for (int q = 0; q < 8; q++) {
            int j = tid + q * 256;
            int mm = j & 127, k2 = j >> 7;
            cvt_pair(r[q * 2], r[q * 2 + 1], H[k2][mm], L[k2][mm]);
        }
    }
}

#define TG_PLANE 2176  // 16*136 words

__global__ __launch_bounds__(256) void tgemm_kernel(GemmP p) {
    extern __shared__ unsigned sm_dyn[];
    int bz = blockIdx.z;
    long long Abase = (long long)bz * p.a_b;
    long long Bbase = (long long)bz * p.b_b;
    int m0 = blockIdx.y * 128, n0 = blockIdx.x * 128;
    int tid = threadIdx.x;
    int warp = tid >> 5, lane = tid & 31;
    int wm = warp >> 2, wn = warp & 3;   // warp tile: 64(m) x 32(n)
    int tig = lane & 3, grp = lane >> 2;
    bool acontig = (p.a_sk == 1);
    bool bcontig = (p.b_sk == 1) && !p.conv;

    float acc[4][4][4];
#pragma unroll
    for (int i = 0; i < 4; i++)
#pragma unroll
        for (int j = 0; j < 4; j++)
#pragma unroll
            for (int r = 0; r < 4; r++) acc[i][j][r] = 0.f;

    float regA[16], regB[16];
    int T = p.K / 32;
    load_tileA(p, Abase, m0, 0, tid, regA);
    load_tileB(p, Bbase, bz, n0, 0, tid, regB);

    for (int t = 0; t < T; t++) {
        int buf = t & 1;
        unsigned (*Ah)[136] = (unsigned(*)[136])(sm_dyn + 0 * TG_PLANE * 2 + buf * TG_PLANE);
        unsigned (*Al)[136] = (unsigned(*)[136])(sm_dyn + 1 * TG_PLANE * 2 + buf * TG_PLANE);
        unsigned (*Bh)[136] = (unsigned(*)[136])(sm_dyn + 2 * TG_PLANE * 2 + buf * TG_PLANE);
        unsigned (*Bl)[136] = (unsigned(*)[136])(sm_dyn + 3 * TG_PLANE * 2 + buf * TG_PLANE);
        sts_tile(Ah, Al, acontig, tid, regA);
        sts_tile(Bh, Bl, bcontig, tid, regB);
        if (t + 1 < T) {  // prefetch next tile; latency hides behind MMA block below
            load_tileA(p, Abase, m0, (t + 1) * 32, tid, regA);
            load_tileB(p, Bbase, bz, n0, (t + 1) * 32, tid, regB);
        }
        __syncthreads();  // buf complete; also guards buffer reuse (2-tile distance)
#pragma unroll
        for (int kc2 = 0; kc2 < 16; kc2 += 8) {
            unsigned ah[4][4], al[4][4], bh[4][2], bl[4][2];
#pragma unroll
            for (int mf = 0; mf < 4; mf++) {
                int mr = wm * 64 + mf * 16 + grp;
                ah[mf][0] = Ah[kc2 + tig][mr];
                ah[mf][1] = Ah[kc2 + tig][mr + 8];
                ah[mf][2] = Ah[kc2 + tig + 4][mr];
                ah[mf][3] = Ah[kc2 + tig + 4][mr + 8];
                al[mf][0] = Al[kc2 + tig][mr];
                al[mf][1] = Al[kc2 + tig][mr + 8];
                al[mf][2] = Al[kc2 + tig + 4][mr];
                al[mf][3] = Al[kc2 + tig + 4][mr + 8];
            }
#pragma unroll
            for (int nf = 0; nf < 4; nf++) {
                int nc = wn * 32 + nf * 8 + grp;
                bh[nf][0] = Bh[kc2 + tig][nc];
                bh[nf][1] = Bh[kc2 + tig + 4][nc];
                bl[nf][0] = Bl[kc2 + tig][nc];
                bl[nf][1] = Bl[kc2 + tig + 4][nc];
            }
#pragma unroll
            for (int mf = 0; mf < 4; mf++)
#pragma unroll
                for (int nf = 0; nf < 4; nf++) {
                    mma16(acc[mf][nf], ah[mf], bh[nf]);
                    mma16(acc[mf][nf], ah[mf], bl[nf]);
                    mma16(acc[mf][nf], al[mf], bh[nf]);
                }
        }
    }

    // ---- epilogue ----
#pragma unroll
    for (int mf = 0; mf < 4; mf++) {
#pragma unroll
        for (int nf = 0; nf < 4; nf++) {
#pragma unroll
            for (int half = 0; half < 2; half++) {
                int m = m0 + wm * 64 + mf * 16 + grp + half * 8;
                int n = n0 + wn * 32 + nf * 8 + tig * 2;
                float v0 = acc[mf][nf][half * 2 + 0];
                float v1 = acc[mf][nf][half * 2 + 1];
                if (p.bias) {
                    if (p.bias_per_m) { float bm = p.bias[m]; v0 += bm; v1 += bm; }
                    else { v0 += p.bias[n]; v1 += p.bias[n + 1]; }
                }
                long long cidx = (long long)bz * p.c_b + (long long)m * p.c_row + n;
                if (p.mode == 0) {
                    *(float2*)&p.C[cidx] = make_float2(v0, v1);
                } else if (p.mode == 1) {
                    int tok = p.tokens[bz * SSQ + m];
                    if (tok == 0) { v0 = 0.f; v1 = 0.f; }
                    *(float2*)&p.C[cidx] = make_float2(v0, v1);
                    float2 e = *(const float2*)&p.emb[(long long)bz * p.emb_b + (long long)m * p.N + n];
                    *(float2*)&p.C2[cidx] = make_float2((v0 + e.x) * R2F, (v1 + e.y) * R2F);
                } else {
                    float2 e = *(const float2*)&p.emb[(long long)bz * p.emb_b + (long long)m * p.N + n];
                    *(float2*)&p.C[cidx] = make_float2((v0 + e.x) * R2F, (v1 + e.y) * R2F);
                }
            }
        }
    }
}

// ---------------- vocab GEMM: 1x tf32, double-buffered (terminal op) ----------------
#define VG_PLANE 4352  // 32*136 words

__global__ __launch_bounds__(256) void vgemm_kernel(const float* __restrict__ A,
                                                    const float* __restrict__ W,
                                                    const float* __restrict__ bias,
                                                    float* __restrict__ C) {
    extern __shared__ unsigned sm_dyn[];
    int m0 = blockIdx.y * 128, n0 = blockIdx.x * 128;
    int tid = threadIdx.x;
    int warp = tid >> 5, lane = tid & 31;
    int wm = warp >> 2, wn = warp & 3;
    int tig = lane & 3, grp = lane >> 2;

    float acc[4][4][4];
#pragma unroll
    for (int i = 0; i < 4; i++)
#pragma unroll
        for (int j = 0; j < 4; j++)
#pragma unroll
            for (int r = 0; r < 4; r++) acc[i][j][r] = 0.f;

    int am = tid >> 1, akb = (tid & 1) << 4;
    float regA[16], regB[16];

    const float* Ap0 = A + (long long)(m0 + am) * DDQ + akb;
#pragma unroll
    for (int u = 0; u < 4; u++) {
        float4 v = *(const float4*)(Ap0 + u * 4);
        regA[u * 4 + 0] = v.x; regA[u * 4 + 1] = v.y; regA[u * 4 + 2] = v.z; regA[u * 4 + 3] = v.w;
    }
#pragma unroll
    for (int q = 0; q < 16; q++) {
        int j = tid + q * 256;
        int nn = j & 127, kk = j >> 7;
        regB[q] = W[(long long)kk * VVQ + n0 + nn];
    }

    int T = DDQ / 32;  // 16
    for (int t = 0; t < T; t++) {
        int buf = t & 1;
        unsigned (*At)[136] = (unsigned(*)[136])(sm_dyn + buf * VG_PLANE);
        unsigned (*Bt)[136] = (unsigned(*)[136])(sm_dyn + 2 * VG_PLANE + buf * VG_PLANE);
#pragma unroll
        for (int u = 0; u < 16; u++) At[akb + u][am] = f2tf(regA[u]);
#pragma unroll
        for (int q = 0; q < 16; q++) {
            int j = tid + q * 256;
            int nn = j & 127, kk = j >> 7;
            Bt[kk][nn] = f2tf(regB[q]);
        }
        if (t + 1 < T) {
            int k0 = (t + 1) * 32;
            const float* Ap = A + (long long)(m0 + am) * DDQ + k0 + akb;
#pragma unroll
            for (int u = 0; u < 4; u++) {
                float4 v = *(const float4*)(Ap + u * 4);
                regA[u * 4 + 0] = v.x; regA[u * 4 + 1] = v.y; regA[u * 4 + 2] = v.z; regA[u * 4 + 3] = v.w;
            }
#pragma unroll
            for (int q = 0; q < 16; q++) {
                int j = tid + q * 256;
                int nn = j & 127, kk = j >> 7;
                regB[q] = W[(long long)(k0 + kk) * VVQ + n0 + nn];
            }
        }
        __syncthreads();
#pragma unroll
        for (int ks = 0; ks < 32; ks += 8) {
            unsigned af[4][4], bf[4][2];
#pragma unroll
            for (int mf = 0; mf < 4; mf++) {
                int mr = wm * 64 + mf * 16 + grp;
                af[mf][0] = At[ks + tig][mr];
                af[mf][1] = At[ks + tig][mr + 8];
                af[mf][2] = At[ks + tig + 4][mr];
                af[mf][3] = At[ks + tig + 4][mr + 8];
            }
#pragma unroll
            for (int nf = 0; nf < 4; nf++) {
                int nc = wn * 32 + nf * 8 + grp;
                bf[nf][0] = Bt[ks + tig][nc];
                bf[nf][1] = Bt[ks + tig + 4][nc];
            }
#pragma unroll
            for (int mf = 0; mf < 4; mf++)
#pragma unroll
                for (int nf = 0; nf < 4; nf++) mma8(acc[mf][nf], af[mf], bf[nf]);
        }
    }

#pragma unroll
    for (int mf = 0; mf < 4; mf++)
#pragma unroll
        for (int nf = 0; nf < 4; nf++)
#pragma unroll
            for (int half = 0; half < 2; half++) {
                int m = m0 + wm * 64 + mf * 16 + grp + half * 8;
                int n = n0 + wn * 32 + nf * 8 + tig * 2;
                float v0 = acc[mf][nf][half * 2 + 0] + bias[n];
                float v1 = acc[mf][nf][half * 2 + 1] + bias[n + 1];
                *(float2*)&C[(long long)m * VVQ + n] = make_float2(v0, v1);
            }
}

// ---------------- embeddings ----------------
__global__ void embed_kernel(const int* __restrict__ tokens, const float* __restrict__ tok_emb,
                             const float* __restrict__ pos_emb, float* __restrict__ out, int Slen) {
    int b = blockIdx.y;
    __shared__ int pos[SSQ];
    if (threadIdx.x == 0) {
        int c = 0;
        for (int s = 0; s < Slen; s++) {
            int m = (tokens[b * Slen + s] != 0) ? 1 : 0;
            c += m;
            pos[s] = c * m;
        }
    }
    __syncthreads();
    int chunk = Slen / gridDim.x;
    int s0 = blockIdx.x * chunk;
    for (int idx = threadIdx.x; idx < chunk * DDQ; idx += blockDim.x) {
        int s = s0 + idx / DDQ;
        int d = idx % DDQ;
        int tk = tokens[b * Slen + s];
        out[((long long)b * Slen + s) * DDQ + d] =
            tok_emb[(long long)tk * DDQ + d] + pos_emb[(long long)pos[s] * DDQ + d];
    }
}

// ---------------- GLU (+ optional residual, in place on x) ----------------
__global__ void glu_res_kernel(const float* __restrict__ y, float* __restrict__ x,
                               int total, int DS, int apply_res) {
    int idx = blockIdx.x * blockDim.x + threadIdx.x;
    if (idx >= total) return;
    int b = idx / DS;
    int rem = idx - b * DS;
    float a = y[(long long)b * 2 * DS + rem];
    float g = y[(long long)b * 2 * DS + DS + rem];
    float v = a / (1.f + expf(-g));
    x[idx] = apply_res ? (v + x[idx]) * R2F : v;
}

// ---------------- decoder combine: x = ((c + att2^T)*R2 + x)*R2 ----------------
__global__ void dec_combine_kernel(float* __restrict__ x, const float* __restrict__ c,
                                   const float* __restrict__ att2, int total) {
    int idx = blockIdx.x * blockDim.x + threadIdx.x;
    if (idx >= total) return;
    int b = idx / (DDQ * TTQ);
    int rem = idx - b * (DDQ * TTQ);
    int ch = rem / TTQ;
    int t = rem % TTQ;
    float cc = (c[idx] + att2[((long long)b * TTQ + t) * DDQ + ch]) * R2F;
    x[idx] = (cc + x[idx]) * R2F;
}

// ---------------- masked softmax over S ----------------
__global__ void softmax_mask_kernel(float* __restrict__ energy, const int* __restrict__ src) {
    int row = blockIdx.x;           // b*T + t
    int b = row / TTQ;
    float* e = energy + (long long)row * SSQ;
    int s = threadIdx.x;            // 256 = S
    float v = (src[b * SSQ + s] == 0) ? -INFINITY : e[s];
    __shared__ float red[SSQ];
    red[s] = v;
    __syncthreads();
    for (int off = 128; off > 0; off >>= 1) {
        if (s < off) red[s] = fmaxf(red[s], red[s + off]);
        __syncthreads();
    }
    float mx = red[0];
    __syncthreads();
    float ex = expf(v - mx);
    red[s] = ex;
    __syncthreads();
    for (int off = 128; off > 0; off >>= 1) {
        if (s < off) red[s] += red[s + off];
        __syncthreads();
    }
    e[s] = ex / red[0];
}

// ---------------- host side ----------------
#define TG_SMEM 69632
#define VG_SMEM 69632

static void gemm(const float* A, long long a_sm, long long a_sk, long long a_b,
                 const float* Bm, long long b_sk, long long b_sn, long long b_b,
                 float* C, long long c_row, long long c_b,
                 const float* bias, int bias_per_m,
                 int M, int N, int K, int nb,
                 int mode = 0, const int* tokens = nullptr,
                 const float* emb = nullptr, long long emb_b = 0, float* C2 = nullptr,
                 int conv = 0, int Slen = 0) {
    GemmP p;
    p.A = A; p.a_sm = a_sm; p.a_sk = a_sk; p.a_b = a_b;
    p.Bm = Bm; p.b_sk = b_sk; p.b_sn = b_sn; p.b_b = b_b;
    p.C = C; p.c_row = c_row; p.c_b = c_b;
    p.bias = bias; p.bias_per_m = bias_per_m;
    p.M = M; p.N = N; p.K = K; p.mode = mode;
    p.tokens = tokens; p.emb = emb; p.emb_b = emb_b; p.C2 = C2;
    p.conv = conv; p.Slen = Slen;
    dim3 grid(N / 128, M / 128, nb);
    tgemm_kernel<<<grid, 256, TG_SMEM>>>(p);
}

extern "C" void kernel_launch(void* const* d_in, const int* in_sizes, int n_in,
                              void* d_out, int out_size) {
    const int*   src        = (const int*)d_in[0];
    const int*   trg        = (const int*)d_in[1];
    const float* enc_tok    = (const float*)d_in[2];
    const float* enc_pos    = (const float*)d_in[3];
    const float* dec_tok    = (const float*)d_in[4];
    const float* dec_pos    = (const float*)d_in[5];
    const float* enc_in_w   = (const float*)d_in[6];
    const float* enc_in_b   = (const float*)d_in[7];
    const float* enc_conv_w = (const float*)d_in[8];
    const float* enc_conv_b = (const float*)d_in[9];
    const float* enc_out_w  = (const float*)d_in[10];
    const float* enc_out_b  = (const float*)d_in[11];
    const float* dec_in_w   = (const float*)d_in[12];
    const float* dec_in_b   = (const float*)d_in[13];
    const float* dec_conv_w = (const float*)d_in[14];
    const float* dec_conv_b = (const float*)d_in[15];
    const float* attn_in_w  = (const float*)d_in[16];
    const float* attn_in_b  = (const float*)d_in[17];
    const float* attn_out_w = (const float*)d_in[18];
    const float* attn_out_b = (const float*)d_in[19];
    const float* dec_out_w  = (const float*)d_in[20];
    const float* dec_out_b  = (const float*)d_in[21];
    const float* vocab_w    = (const float*)d_in[22];
    const float* vocab_b    = (const float*)d_in[23];
    float* logits = (float*)d_out;

    cudaFuncSetAttribute(tgemm_kernel, cudaFuncAttributeMaxDynamicSharedMemorySize, TG_SMEM);
    cudaFuncSetAttribute(vgemm_kernel, cudaFuncAttributeMaxDynamicSharedMemorySize, VG_SMEM);

    void* sp;
    cudaGetSymbolAddress(&sp, g_scratch);
    float* base = (float*)sp;
    float* enc_emb    = base;
    float* enc_x      = base + 2097152;
    float* ybuf       = base + 10485760;
    float* enc_conved = base + 14680064;
    float* enc_comb   = base + 16777216;
    float* dec_emb    = base + 18874368;
    float* dec_x      = base + 19922944;
    float* dec_c      = base + 20971520;
    float* qbuf       = base + 22020096;
    float* energy     = base + 23068672;
    float* att        = base + 23592960;
    float* att2       = base + 24641536;

    // ---- embeddings ----
    embed_kernel<<<dim3(4, BB), 256>>>(src, enc_tok, enc_pos, enc_emb, SSQ);
    embed_kernel<<<dim3(4, BB), 256>>>(trg, dec_tok, dec_pos, dec_emb, TTQ);

    // ---- encoder in-projection -> x[b][c][s] ----
    gemm(enc_in_w, 1, DDQ, 0,
         enc_emb, 1, DDQ, (long long)SSQ * DDQ,
         enc_x, SSQ, (long long)DDQ * SSQ,
         enc_in_b, 1, DDQ, SSQ, DDQ, BB);

    // ---- encoder conv stack (fused im2col) ----
    for (int l = 0; l < LLQ; l++) {
        gemm(enc_conv_w + (long long)l * 2 * DDQ * DDQ * 3, 3 * DDQ, 1, 0,
             enc_x, 0, 0, (long long)DDQ * SSQ,
             ybuf, SSQ, (long long)2 * DDQ * SSQ,
             enc_conv_b + l * 2 * DDQ, 1, 2 * DDQ, SSQ, 3 * DDQ, BB,
             0, src, nullptr, 0, nullptr, 1, SSQ);
        int tot2 = BB * DDQ * SSQ;
        glu_res_kernel<<<(tot2 + 255) / 256, 256>>>(ybuf, enc_x, tot2, DDQ * SSQ, 1);
    }

    // ---- encoder out-projection (+pad mask, combined) ----
    gemm(enc_x, 1, SSQ, (long long)DDQ * SSQ,
         enc_out_w, DDQ, 1, 0,
         enc_conved, DDQ, (long long)SSQ * DDQ,
         enc_out_b, 0, SSQ, DDQ, DDQ, BB,
         1, src, enc_emb, (long long)SSQ * DDQ, enc_comb);

    // ---- decoder in-projection -> x[b][c][t] ----
    gemm(dec_in_w, 1, DDQ, 0,
         dec_emb, 1, DDQ, (long long)TTQ * DDQ,
         dec_x, TTQ, (long long)DDQ * TTQ,
         dec_in_b, 1, DDQ, TTQ, DDQ, BB);

    // ---- decoder layers ----
    for (int l = 0; l < LLQ; l++) {
        gemm(dec_conv_w + (long long)l * 2 * DDQ * DDQ * 3, 3 * DDQ, 1, 0,
             dec_x, 0, 0, (long long)DDQ * TTQ,
             ybuf, TTQ, (long long)2 * DDQ * TTQ,
             dec_conv_b + l * 2 * DDQ, 1, 2 * DDQ, TTQ, 3 * DDQ, BB,
             0, nullptr, nullptr, 0, nullptr, 2, TTQ);
        int tot2 = BB * DDQ * TTQ;
        glu_res_kernel<<<(tot2 + 255) / 256, 256>>>(ybuf, dec_c, tot2, DDQ * TTQ, 0);

        // q = (c^T @ Wq + bq + emb) * R2
        gemm(dec_c, 1, TTQ, (long long)DDQ * TTQ,
             attn_in_w + (long long)l * DDQ * DDQ, DDQ, 1, 0,
             qbuf, DDQ, (long long)TTQ * DDQ,
             attn_in_b + l * DDQ, 0, TTQ, DDQ, DDQ, BB,
             2, nullptr, dec_emb, (long long)TTQ * DDQ, nullptr);

        // energy = q @ enc_conved^T
        gemm(qbuf, DDQ, 1, (long long)TTQ * DDQ,
             enc_conved, 1, DDQ, (long long)SSQ * DDQ,
             energy, SSQ, (long long)TTQ * SSQ,
             nullptr, 0, TTQ, SSQ, DDQ, BB);

        softmax_mask_kernel<<<BB * TTQ, SSQ>>>(energy, src);

        // att = attn @ enc_combined
        gemm(energy, SSQ, 1, (long long)TTQ * SSQ,
             enc_comb, DDQ, 1, (long long)SSQ * DDQ,
             att, DDQ, (long long)TTQ * DDQ,
             nullptr, 0, TTQ, DDQ, SSQ, BB);

        // att2 = att @ Wout + bout
        gemm(att, DDQ, 1, 0,
             attn_out_w + (long long)l * DDQ * DDQ, DDQ, 1, 0,
             att2, DDQ, 0,
             attn_out_b + l * DDQ, 0, BB * TTQ, DDQ, DDQ, 1);

        int tot3 = BB * DDQ * TTQ;
        dec_combine_kernel<<<(tot3 + 255) / 256, 256>>>(dec_x, dec_c, att2, tot3);
    }

    // ---- decoder out-projection -> [B,T,D] (reuse qbuf) ----
    gemm(dec_x, 1, TTQ, (long long)DDQ * TTQ,
         dec_out_w, DDQ, 1, 0,
         qbuf, DDQ, (long long)TTQ * DDQ,
         dec_out_b, 0, TTQ, DDQ, DDQ, BB);

    // ---- vocab projection -> logits [B*T, V] ----
    vgemm_kernel<<<dim3(VVQ / 128, (BB * TTQ) / 128), 256, VG_SMEM>>>(qbuf, vocab_w, vocab_b, logits);
}

// round 10
// speedup vs baseline: 1.0990x; 1.0990x over previous
#include <cuda_runtime.h>
#include <cuda_bf16.h>
#include <math.h>

#define BB 16
#define SSQ 256
#define TTQ 128
#define DDQ 512
#define VVQ 32000
#define LLQ 3
#define R2F 0.70710678118654752440f

// ---------------- scratch (single __device__ array, no allocs) ----------------
__device__ float g_scratch[25690112];

// ---------------- bf16 split-pair tensor-core batched GEMM (128x64 tile) ----------------
struct GemmP {
    const float* A; long long a_sm, a_sk, a_b;
    const float* Bm; long long b_sk, b_sn, b_b;
    float* C; long long c_row, c_b;
    const float* bias; int bias_per_m;
    int M, N, K, mode;           // mode: 0 plain, 1 enc-out (pad zero + combined), 2 (+emb)*R2
    const int* tokens;
    const float* emb; long long emb_b;
    float* C2;
};

__device__ __forceinline__ unsigned f2tf(float x) {
    unsigned r;
    asm("cvt.rna.tf32.f32 %0, %1;" : "=r"(r) : "f"(x));
    return r;
}

__device__ __forceinline__ void cvt_pair(float x0, float x1, unsigned& hw, unsigned& lw) {
    __nv_bfloat162 h = __floats2bfloat162_rn(x0, x1);
    float2 hf = __bfloat1622float2(h);
    __nv_bfloat162 l = __floats2bfloat162_rn(x0 - hf.x, x1 - hf.y);
    hw = *reinterpret_cast<unsigned*>(&h);
    lw = *reinterpret_cast<unsigned*>(&l);
}

__device__ __forceinline__ void mma16(float* d, const unsigned* a, const unsigned* b) {
    asm volatile(
        "mma.sync.aligned.m16n8k16.row.col.f32.bf16.bf16.f32 "
        "{%0,%1,%2,%3}, {%4,%5,%6,%7}, {%8,%9}, {%0,%1,%2,%3};"
        : "+f"(d[0]), "+f"(d[1]), "+f"(d[2]), "+f"(d[3])
        : "r"(a[0]), "r"(a[1]), "r"(a[2]), "r"(a[3]), "r"(b[0]), "r"(b[1]));
}

__device__ __forceinline__ void mma8(float* d, const unsigned* a, const unsigned* b) {
    asm volatile(
        "mma.sync.aligned.m16n8k8.row.col.f32.tf32.tf32.f32 "
        "{%0,%1,%2,%3}, {%4,%5,%6,%7}, {%8,%9}, {%0,%1,%2,%3};"
        : "+f"(d[0]), "+f"(d[1]), "+f"(d[2]), "+f"(d[3])
        : "r"(a[0]), "r"(a[1]), "r"(a[2]), "r"(a[3]), "r"(b[0]), "r"(b[1]));
}

// ---- A tile: 128(m) x 32(k) into 16 regs ----
__device__ __forceinline__ void load_tileA(const GemmP& p, long long base, int m0, int k0,
                                           int tid, float* r) {
    if (p.a_sk == 1) {
        int mm = tid >> 1, kb = (tid & 1) << 4;
        const float* q = p.A + base + (long long)(m0 + mm) * p.a_sm + k0 + kb;
#pragma unroll
        for (int u = 0; u < 4; u++) {
            float4 v = *(const float4*)(q + u * 4);
            r[u * 4 + 0] = v.x; r[u * 4 + 1] = v.y; r[u * 4 + 2] = v.z; r[u * 4 + 3] = v.w;
        }
    } else {
#pragma unroll
        for (int q = 0; q < 8; q++) {
            int j = tid + q * 256;
            int mm = j & 127, k2 = j >> 7;
            long long b2 = base + (long long)(m0 + mm) * p.a_sm;
            r[q * 2]     = p.A[b2 + (long long)(k0 + 2 * k2) * p.a_sk];
            r[q * 2 + 1] = p.A[b2 + (long long)(k0 + 2 * k2 + 1) * p.a_sk];
        }
    }
}

__device__ __forceinline__ void sts_tileA(unsigned (*H)[136], unsigned (*L)[136],
                                          bool contig, int tid, const float* r) {
    if (contig) {
        int mm = tid >> 1, kb2 = (tid & 1) << 3;
#pragma unroll
        for (int u = 0; u < 8; u++)
            cvt_pair(r[u * 2], r[u * 2 + 1], H[kb2 + u][mm], L[kb2 + u][mm]);
    } else {
#pragma unroll
        for (int q = 0; q < 8; q++) {
            int j = tid + q * 256;
            int mm = j & 127, k2 = j >> 7;
            cvt_pair(r[q * 2], r[q * 2 + 1], H[k2][mm], L[k2][mm]);
        }
    }
}

// ---- B tile: 64(n) x 32(k) into 8 regs ----
__device__ __forceinline__ void load_tileB(const GemmP& p, long long base, int n0, int k0,
                                           int tid, float* r) {
    if (p.b_sk == 1) {
        int nn = tid >> 2, kb = (tid & 3) << 3;
        const float* q = p.Bm + base + (long long)(n0 + nn) * p.b_sn + k0 + kb;
#pragma unroll
        for (int u = 0; u < 2; u++) {
            float4 v = *(const float4*)(q + u * 4);
            r[u * 4 + 0] = v.x; r[u * 4 + 1] = v.y; r[u * 4 + 2] = v.z; r[u * 4 + 3] = v.w;
        }
    } else {
#pragma unroll
        for (int q = 0; q < 4; q++) {
            int j = tid + q * 256;
            int nn = j & 63, k2 = j >> 6;
            long long b2 = base + (long long)(n0 + nn) * p.b_sn;
            r[q * 2]     = p.Bm[b2 + (long long)(k0 + 2 * k2) * p.b_sk];
            r[q * 2 + 1] = p.Bm[b2 + (long long)(k0 + 2 * k2 + 1) * p.b_sk];
        }
    }
}

__device__ __forceinline__ void sts_tileB(unsigned (*H)[72], unsigned (*L)[72],
                                          bool contig, int tid, const float* r) {
    if (contig) {
        int nn = tid >> 2, kb2 = (tid & 3) << 1;
#pragma unroll
        for (int u = 0; u < 2; u++) {
            cvt_pair(r[u * 4 + 0], r[u * 4 + 1], H[kb2 + u * 8 + 0][nn], L[kb2 + u * 8 + 0][nn]);
            cvt_pair(r[u * 4 + 2], r[u * 4 + 3], H[kb2 + u * 8 + 1][nn], L[kb2 + u * 8 + 1][nn]);
        }
    } else {
#pragma unroll
        for (int q = 0; q < 4; q++) {
            int j = tid + q * 256;
            int nn = j & 63, k2 = j >> 6;
            cvt_pair(r[q * 2], r[q * 2 + 1], H[k2][nn], L[k2][nn]);
        }
    }
}
// NOTE contig-B STS: thread owns k = (tid&3)*8..+7 -> k2 rows {2(tid&3), 2(tid&3)+1} and
// k = 16+(tid&3)*8?? -- careful: kb=(tid&3)<<3 gives k in [kb, kb+8): k2 rows kb/2 .. kb/2+3
// = {2(tid&3)*2 ...}. Corrected mapping below is what's used: kb2 = (tid&3)<<1 covers rows
// {kb2, kb2+1} for u=0 (k kb..kb+3) and rows {kb2+8, kb2+9}?? -> see sts layout note: with
// kb=(tid&3)*8, k2 = 4*(tid&3) + {0,1,2,3}. The mapping above is WRONG for that; fixed here:

__device__ __forceinline__ void sts_tileB_contig_fixed(unsigned (*H)[72], unsigned (*L)[72],
                                                       int tid, const float* r) {
    int nn = tid >> 2, kb2 = (tid & 3) << 2;  // k2 rows kb2..kb2+3
#pragma unroll
    for (int u = 0; u < 4; u++)
        cvt_pair(r[u * 2], r[u * 2 + 1], H[kb2 + u][nn], L[kb2 + u][nn]);
}

__global__ __launch_bounds__(256, 2) void tgemm_kernel(GemmP p) {
    __shared__ unsigned Ah[16][136], Al[16][136];
    __shared__ unsigned Bh[16][72], Bl[16][72];
    int bz = blockIdx.z;
    long long Abase = (long long)bz * p.a_b;
    long long Bbase = (long long)bz * p.b_b;
    int m0 = blockIdx.y * 128, n0 = blockIdx.x * 64;
    int tid = threadIdx.x;
    int warp = tid >> 5, lane = tid & 31;
    int wm = warp >> 1, wn = warp & 1;   // 4x2 warps; warp tile 32(m) x 32(n)
    int tig = lane & 3, grp = lane >> 2;
    bool acontig = (p.a_sk == 1);
    bool bcontig = (p.b_sk == 1);

    float acc[2][4][4];
#pragma unroll
    for (int i = 0; i < 2; i++)
#pragma unroll
        for (int j = 0; j < 4; j++)
#pragma unroll
            for (int r = 0; r < 4; r++) acc[i][j][r] = 0.f;

    float regA[16], regB[8];
    int T = p.K / 32;
    load_tileA(p, Abase, m0, 0, tid, regA);
    load_tileB(p, Bbase, n0, 0, tid, regB);

    for (int t = 0; t < T; t++) {
        sts_tileA(Ah, Al, acontig, tid, regA);
        if (bcontig) sts_tileB_contig_fixed(Bh, Bl, tid, regB);
        else         sts_tileB(Bh, Bl, false, tid, regB);
        __syncthreads();
        if (t + 1 < T) {  // prefetch; LDG latency hides behind MMA block below
            load_tileA(p, Abase, m0, (t + 1) * 32, tid, regA);
            load_tileB(p, Bbase, n0, (t + 1) * 32, tid, regB);
        }
#pragma unroll
        for (int kc2 = 0; kc2 < 16; kc2 += 8) {
            unsigned ah[2][4], al[2][4], bh[4][2], bl[4][2];
#pragma unroll
            for (int mf = 0; mf < 2; mf++) {
                int mr = wm * 32 + mf * 16 + grp;
                ah[mf][0] = Ah[kc2 + tig][mr];
                ah[mf][1] = Ah[kc2 + tig][mr + 8];
                ah[mf][2] = Ah[kc2 + tig + 4][mr];
                ah[mf][3] = Ah[kc2 + tig + 4][mr + 8];
                al[mf][0] = Al[kc2 + tig][mr];
                al[mf][1] = Al[kc2 + tig][mr + 8];
                al[mf][2] = Al[kc2 + tig + 4][mr];
                al[mf][3] = Al[kc2 + tig + 4][mr + 8];
            }
#pragma unroll
            for (int nf = 0; nf < 4; nf++) {
                int nc = wn * 32 + nf * 8 + grp;
                bh[nf][0] = Bh[kc2 + tig][nc];
                bh[nf][1] = Bh[kc2 + tig + 4][nc];
                bl[nf][0] = Bl[kc2 + tig][nc];
                bl[nf][1] = Bl[kc2 + tig + 4][nc];
            }
#pragma unroll
            for (int mf = 0; mf < 2; mf++)
#pragma unroll
                for (int nf = 0; nf < 4; nf++) {
                    mma16(acc[mf][nf], ah[mf], bh[nf]);
                    mma16(acc[mf][nf], ah[mf], bl[nf]);
                    mma16(acc[mf][nf], al[mf], bh[nf]);
                }
        }
        __syncthreads();
    }

    // ---- epilogue ----
#pragma unroll
    for (int mf = 0; mf < 2; mf++) {
#pragma unroll
        for (int nf = 0; nf < 4; nf++) {
#pragma unroll
            for (int half = 0; half < 2; half++) {
                int m = m0 + wm * 32 + mf * 16 + grp + half * 8;
                int n = n0 + wn * 32 + nf * 8 + tig * 2;
                float v0 = acc[mf][nf][half * 2 + 0];
                float v1 = acc[mf][nf][half * 2 + 1];
                if (p.bias) {
                    if (p.bias_per_m) { float bm = p.bias[m]; v0 += bm; v1 += bm; }
                    else { v0 += p.bias[n]; v1 += p.bias[n + 1]; }
                }
                long long cidx = (long long)bz * p.c_b + (long long)m * p.c_row + n;
                if (p.mode == 0) {
                    *(float2*)&p.C[cidx] = make_float2(v0, v1);
                } else if (p.mode == 1) {
                    int tok = p.tokens[bz * SSQ + m];
                    if (tok == 0) { v0 = 0.f; v1 = 0.f; }
                    *(float2*)&p.C[cidx] = make_float2(v0, v1);
                    float2 e = *(const float2*)&p.emb[(long long)bz * p.emb_b + (long long)m * p.N + n];
                    *(float2*)&p.C2[cidx] = make_float2((v0 + e.x) * R2F, (v1 + e.y) * R2F);
                } else {
                    float2 e = *(const float2*)&p.emb[(long long)bz * p.emb_b + (long long)m * p.N + n];
                    *(float2*)&p.C[cidx] = make_float2((v0 + e.x) * R2F, (v1 + e.y) * R2F);
                }
            }
        }
    }
}

// ---------------- vocab GEMM: 1x tf32, pipelined (R7-proven) ----------------
__global__ __launch_bounds__(256) void vgemm_kernel(const float* __restrict__ A,
                                                    const float* __restrict__ W,
                                                    const float* __restrict__ bias,
                                                    float* __restrict__ C) {
    __shared__ unsigned At[32][136], Bt[32][136];
    int m0 = blockIdx.y * 128, n0 = blockIdx.x * 128;
    int tid = threadIdx.x;
    int warp = tid >> 5, lane = tid & 31;
    int wm = warp >> 2, wn = warp & 3;
    int tig = lane & 3, grp = lane >> 2;

    float acc[4][4][4];
#pragma unroll
    for (int i = 0; i < 4; i++)
#pragma unroll
        for (int j = 0; j < 4; j++)
#pragma unroll
            for (int r = 0; r < 4; r++) acc[i][j][r] = 0.f;

    int am = tid >> 1, akb = (tid & 1) << 4;
    float regA[16], regB[16];

    const float* Ap0 = A + (long long)(m0 + am) * DDQ + akb;
#pragma unroll
    for (int u = 0; u < 4; u++) {
        float4 v = *(const float4*)(Ap0 + u * 4);
        regA[u * 4 + 0] = v.x; regA[u * 4 + 1] = v.y; regA[u * 4 + 2] = v.z; regA[u * 4 + 3] = v.w;
    }
#pragma unroll
    for (int q = 0; q < 16; q++) {
        int j = tid + q * 256;
        int nn = j & 127, kk = j >> 7;
        regB[q] = W[(long long)kk * VVQ + n0 + nn];
    }

    int T = DDQ / 32;  // 16
    for (int t = 0; t < T; t++) {
#pragma unroll
        for (int u = 0; u < 16; u++) At[akb + u][am] = f2tf(regA[u]);
#pragma unroll
        for (int q = 0; q < 16; q++) {
            int j = tid + q * 256;
            int nn = j & 127, kk = j >> 7;
            Bt[kk][nn] = f2tf(regB[q]);
        }
        __syncthreads();
        if (t + 1 < T) {
            int k0 = (t + 1) * 32;
            const float* Ap = A + (long long)(m0 + am) * DDQ + k0 + akb;
#pragma unroll
            for (int u = 0; u < 4; u++) {
                float4 v = *(const float4*)(Ap + u * 4);
                regA[u * 4 + 0] = v.x; regA[u * 4 + 1] = v.y; regA[u * 4 + 2] = v.z; regA[u * 4 + 3] = v.w;
            }
#pragma unroll
            for (int q = 0; q < 16; q++) {
                int j = tid + q * 256;
                int nn = j & 127, kk = j >> 7;
                regB[q] = W[(long long)(k0 + kk) * VVQ + n0 + nn];
            }
        }
#pragma unroll
        for (int ks = 0; ks < 32; ks += 8) {
            unsigned af[4][4], bf[4][2];
#pragma unroll
            for (int mf = 0; mf < 4; mf++) {
                int mr = wm * 64 + mf * 16 + grp;
                af[mf][0] = At[ks + tig][mr];
                af[mf][1] = At[ks + tig][mr + 8];
                af[mf][2] = At[ks + tig + 4][mr];
                af[mf][3] = At[ks + tig + 4][mr + 8];
            }
#pragma unroll
            for (int nf = 0; nf < 4; nf++) {
                int nc = wn * 32 + nf * 8 + grp;
                bf[nf][0] = Bt[ks + tig][nc];
                bf[nf][1] = Bt[ks + tig + 4][nc];
            }
#pragma unroll
            for (int mf = 0; mf < 4; mf++)
#pragma unroll
                for (int nf = 0; nf < 4; nf++) mma8(acc[mf][nf], af[mf], bf[nf]);
        }
        __syncthreads();
    }

#pragma unroll
    for (int mf = 0; mf < 4; mf++)
#pragma unroll
        for (int nf = 0; nf < 4; nf++)
#pragma unroll
            for (int half = 0; half < 2; half++) {
                int m = m0 + wm * 64 + mf * 16 + grp + half * 8;
                int n = n0 + wn * 32 + nf * 8 + tig * 2;
                float v0 = acc[mf][nf][half * 2 + 0] + bias[n];
                float v1 = acc[mf][nf][half * 2 + 1] + bias[n + 1];
                *(float2*)&C[(long long)m * VVQ + n] = make_float2(v0, v1);
            }
}

// ---------------- embeddings ----------------
__global__ void embed_kernel(const int* __restrict__ tokens, const float* __restrict__ tok_emb,
                             const float* __restrict__ pos_emb, float* __restrict__ out, int Slen) {
    int b = blockIdx.y;
    __shared__ int pos[SSQ];
    if (threadIdx.x == 0) {
        int c = 0;
        for (int s = 0; s < Slen; s++) {
            int m = (tokens[b * Slen + s] != 0) ? 1 : 0;
            c += m;
            pos[s] = c * m;
        }
    }
    __syncthreads();
    int chunk = Slen / gridDim.x;
    int s0 = blockIdx.x * chunk;
    for (int idx = threadIdx.x; idx < chunk * DDQ; idx += blockDim.x) {
        int s = s0 + idx / DDQ;
        int d = idx % DDQ;
        int tk = tokens[b * Slen + s];
        out[((long long)b * Slen + s) * DDQ + d] =
            tok_emb[(long long)tk * DDQ + d] + pos_emb[(long long)pos[s] * DDQ + d];
    }
}

// ---------------- im2col (row order ic*3+k so weights are contiguous) ----------------
__global__ void im2col_enc_kernel(const float* __restrict__ x, const int* __restrict__ tokens,
                                  float* __restrict__ out, int total) {
    int idx = blockIdx.x * blockDim.x + threadIdx.x;
    if (idx >= total) return;
    int s = idx % SSQ;
    int r = (idx / SSQ) % (3 * DDQ);
    int b = idx / (SSQ * 3 * DDQ);
    int ic = r / 3, k = r % 3;
    int s2 = s + k - 1;
    float v = 0.f;
    if (s2 >= 0 && s2 < SSQ && tokens[b * SSQ + s2] != 0)
        v = x[((long long)b * DDQ + ic) * SSQ + s2];
    out[idx] = v;
}

__global__ void im2col_dec_kernel(const float* __restrict__ x, float* __restrict__ out, int total) {
    int idx = blockIdx.x * blockDim.x + threadIdx.x;
    if (idx >= total) return;
    int t = idx % TTQ;
    int r = (idx / TTQ) % (3 * DDQ);
    int b = idx / (TTQ * 3 * DDQ);
    int ic = r / 3, k = r % 3;
    int t2 = t + k - 2;  // causal: pad K-1=2 left
    out[idx] = (t2 >= 0) ? x[((long long)b * DDQ + ic) * TTQ + t2] : 0.f;
}

// ---------------- GLU (+ optional residual, in place on x) ----------------
__global__ void glu_res_kernel(const float* __restrict__ y, float* __restrict__ x,
                               int total, int DS, int apply_res) {
    int idx = blockIdx.x * blockDim.x + threadIdx.x;
    if (idx >= total) return;
    int b = idx / DS;
    int rem = idx - b * DS;
    float a = y[(long long)b * 2 * DS + rem];
    float g = y[(long long)b * 2 * DS + DS + rem];
    float v = a / (1.f + expf(-g));
    x[idx] = apply_res ? (v + x[idx]) * R2F : v;
}

// ---------------- decoder combine: x = ((c + att2^T)*R2 + x)*R2 ----------------
__global__ void dec_combine_kernel(float* __restrict__ x, const float* __restrict__ c,
                                   const float* __restrict__ att2, int total) {
    int idx = blockIdx.x * blockDim.x + threadIdx.x;
    if (idx >= total) return;
    int b = idx / (DDQ * TTQ);
    int rem = idx - b * (DDQ * TTQ);
    int ch = rem / TTQ;
    int t = rem % TTQ;
    float cc = (c[idx] + att2[((long long)b * TTQ + t) * DDQ + ch]) * R2F;
    x[idx] = (cc + x[idx]) * R2F;
}

// ---------------- masked softmax over S ----------------
__global__ void softmax_mask_kernel(float* __restrict__ energy, const int* __restrict__ src) {
    int row = blockIdx.x;           // b*T + t
    int b = row / TTQ;
    float* e = energy + (long long)row * SSQ;
    int s = threadIdx.x;            // 256 = S
    float v = (src[b * SSQ + s] == 0) ? -INFINITY : e[s];
    __shared__ float red[SSQ];
    red[s] = v;
    __syncthreads();
    for (int off = 128; off > 0; off >>= 1) {
        if (s < off) red[s] = fmaxf(red[s], red[s + off]);
        __syncthreads();
    }
    float mx = red[0];
    __syncthreads();
    float ex = expf(v - mx);
    red[s] = ex;
    __syncthreads();
    for (int off = 128; off > 0; off >>= 1) {
        if (s < off) red[s] += red[s + off];
        __syncthreads();
    }
    e[s] = ex / red[0];
}

// ---------------- host side ----------------
static void gemm(const float* A, long long a_sm, long long a_sk, long long a_b,
                 const float* Bm, long long b_sk, long long b_sn, long long b_b,
                 float* C, long long c_row, long long c_b,
                 const float* bias, int bias_per_m,
                 int M, int N, int K, int nb,
                 int mode = 0, const int* tokens = nullptr,
                 const float* emb = nullptr, long long emb_b = 0, float* C2 = nullptr) {
    GemmP p;
    p.A = A; p.a_sm = a_sm; p.a_sk = a_sk; p.a_b = a_b;
    p.Bm = Bm; p.b_sk = b_sk; p.b_sn = b_sn; p.b_b = b_b;
    p.C = C; p.c_row = c_row; p.c_b = c_b;
    p.bias = bias; p.bias_per_m = bias_per_m;
    p.M = M; p.N = N; p.K = K; p.mode = mode;
    p.tokens = tokens; p.emb = emb; p.emb_b = emb_b; p.C2 = C2;
    dim3 grid(N / 64, M / 128, nb);
    tgemm_kernel<<<grid, 256>>>(p);
}

extern "C" void kernel_launch(void* const* d_in, const int* in_sizes, int n_in,
                              void* d_out, int out_size) {
    const int*   src        = (const int*)d_in[0];
    const int*   trg        = (const int*)d_in[1];
    const float* enc_tok    = (const float*)d_in[2];
    const float* enc_pos    = (const float*)d_in[3];
    const float* dec_tok    = (const float*)d_in[4];
    const float* dec_pos    = (const float*)d_in[5];
    const float* enc_in_w   = (const float*)d_in[6];
    const float* enc_in_b   = (const float*)d_in[7];
    const float* enc_conv_w = (const float*)d_in[8];
    const float* enc_conv_b = (const float*)d_in[9];
    const float* enc_out_w  = (const float*)d_in[10];
    const float* enc_out_b  = (const float*)d_in[11];
    const float* dec_in_w   = (const float*)d_in[12];
    const float* dec_in_b   = (const float*)d_in[13];
    const float* dec_conv_w = (const float*)d_in[14];
    const float* dec_conv_b = (const float*)d_in[15];
    const float* attn_in_w  = (const float*)d_in[16];
    const float* attn_in_b  = (const float*)d_in[17];
    const float* attn_out_w = (const float*)d_in[18];
    const float* attn_out_b = (const float*)d_in[19];
    const float* dec_out_w  = (const float*)d_in[20];
    const float* dec_out_b  = (const float*)d_in[21];
    const float* vocab_w    = (const float*)d_in[22];
    const float* vocab_b    = (const float*)d_in[23];
    float* logits = (float*)d_out;

    void* sp;
    cudaGetSymbolAddress(&sp, g_scratch);
    float* base = (float*)sp;
    float* enc_emb    = base;
    float* enc_x      = base + 2097152;
    float* im2col     = base + 4194304;
    float* ybuf       = base + 10485760;
    float* enc_conved = base + 14680064;
    float* enc_comb   = base + 16777216;
    float* dec_emb    = base + 18874368;
    float* dec_x      = base + 19922944;
    float* dec_c      = base + 20971520;
    float* qbuf       = base + 22020096;
    float* energy     = base + 23068672;
    float* att        = base + 23592960;
    float* att2       = base + 24641536;

    // ---- embeddings ----
    embed_kernel<<<dim3(4, BB), 256>>>(src, enc_tok, enc_pos, enc_emb, SSQ);
    embed_kernel<<<dim3(4, BB), 256>>>(trg, dec_tok, dec_pos, dec_emb, TTQ);

    // ---- encoder in-projection -> x[b][c][s] ----
    gemm(enc_in_w, 1, DDQ, 0,
         enc_emb, 1, DDQ, (long long)SSQ * DDQ,
         enc_x, SSQ, (long long)DDQ * SSQ,
         enc_in_b, 1, DDQ, SSQ, DDQ, BB);

    // ---- encoder conv stack ----
    for (int l = 0; l < LLQ; l++) {
        int tot = BB * DDQ * 3 * SSQ;
        im2col_enc_kernel<<<(tot + 255) / 256, 256>>>(enc_x, src, im2col, tot);
        gemm(enc_conv_w + (long long)l * 2 * DDQ * DDQ * 3, 3 * DDQ, 1, 0,
             im2col, SSQ, 1, (long long)3 * DDQ * SSQ,
             ybuf, SSQ, (long long)2 * DDQ * SSQ,
             enc_conv_b + l * 2 * DDQ, 1, 2 * DDQ, SSQ, 3 * DDQ, BB);
        int tot2 = BB * DDQ * SSQ;
        glu_res_kernel<<<(tot2 + 255) / 256, 256>>>(ybuf, enc_x, tot2, DDQ * SSQ, 1);
    }

    // ---- encoder out-projection (+pad mask, combined) ----
    gemm(enc_x, 1, SSQ, (long long)DDQ * SSQ,
         enc_out_w, DDQ, 1, 0,
         enc_conved, DDQ, (long long)SSQ * DDQ,
         enc_out_b, 0, SSQ, DDQ, DDQ, BB,
         1, src, enc_emb, (long long)SSQ * DDQ, enc_comb);

    // ---- decoder in-projection -> x[b][c][t] ----
    gemm(dec_in_w, 1, DDQ, 0,
         dec_emb, 1, DDQ, (long long)TTQ * DDQ,
         dec_x, TTQ, (long long)DDQ * TTQ,
         dec_in_b, 1, DDQ, TTQ, DDQ, BB);

    // ---- decoder layers ----
    for (int l = 0; l < LLQ; l++) {
        int tot = BB * DDQ * 3 * TTQ;
        im2col_dec_kernel<<<(tot + 255) / 256, 256>>>(dec_x, im2col, tot);
        gemm(dec_conv_w + (long long)l * 2 * DDQ * DDQ * 3, 3 * DDQ, 1, 0,
             im2col, TTQ, 1, (long long)3 * DDQ * TTQ,
             ybuf, TTQ, (long long)2 * DDQ * TTQ,
             dec_conv_b + l * 2 * DDQ, 1, 2 * DDQ, TTQ, 3 * DDQ, BB);
        int tot2 = BB * DDQ * TTQ;
        glu_res_kernel<<<(tot2 + 255) / 256, 256>>>(ybuf, dec_c, tot2, DDQ * TTQ, 0);

        // q = (c^T @ Wq + bq + emb) * R2
        gemm(dec_c, 1, TTQ, (long long)DDQ * TTQ,
             attn_in_w + (long long)l * DDQ * DDQ, DDQ, 1, 0,
             qbuf, DDQ, (long long)TTQ * DDQ,
             attn_in_b + l * DDQ, 0, TTQ, DDQ, DDQ, BB,
             2, nullptr, dec_emb, (long long)TTQ * DDQ, nullptr);

        // energy = q @ enc_conved^T
        gemm(qbuf, DDQ, 1, (long long)TTQ * DDQ,
             enc_conved, 1, DDQ, (long long)SSQ * DDQ,
             energy, SSQ, (long long)TTQ * SSQ,
             nullptr, 0, TTQ, SSQ, DDQ, BB);

        softmax_mask_kernel<<<BB * TTQ, SSQ>>>(energy, src);

        // att = attn @ enc_combined
        gemm(energy, SSQ, 1, (long long)TTQ * SSQ,
             enc_comb, DDQ, 1, (long long)SSQ * DDQ,
             att, DDQ, (long long)TTQ * DDQ,
             nullptr, 0, TTQ, DDQ, SSQ, BB);

        // att2 = att @ Wout + bout
        gemm(att, DDQ, 1, 0,
             attn_out_w + (long long)l * DDQ * DDQ, DDQ, 1, 0,
             att2, DDQ, 0,
             attn_out_b + l * DDQ, 0, BB * TTQ, DDQ, DDQ, 1);

        int tot3 = BB * DDQ * TTQ;
        dec_combine_kernel<<<(tot3 + 255) / 256, 256>>>(dec_x, dec_c, att2, tot3);
    }

    // ---- decoder out-projection -> [B,T,D] (reuse qbuf) ----
    gemm(dec_x, 1, TTQ, (long long)DDQ * TTQ,
         dec_out_w, DDQ, 1, 0,
         qbuf, DDQ, (long long)TTQ * DDQ,
         dec_out_b, 0, TTQ, DDQ, DDQ, BB);

    // ---- vocab projection -> logits [B*T, V] ----
    vgemm_kernel<<<dim3(VVQ / 128, (BB * TTQ) / 128), 256>>>(qbuf, vocab_w, vocab_b, logits);
}

// round 13
// speedup vs baseline: 1.1088x; 1.0089x over previous
#include <cuda_runtime.h>
#include <cuda_bf16.h>
#include <math.h>

#define BB 16
#define SSQ 256
#define TTQ 128
#define DDQ 512
#define VVQ 32000
#define LLQ 3
#define R2F 0.70710678118654752440f

// ---------------- scratch (single __device__ array, no allocs) ----------------
__device__ float g_scratch[25690112];

// ---------------- tensor-core batched GEMM (128x64 tile, 2 CTAs/SM) --------------
// SPLITS=3: bf16 split-pair (fp32-class accuracy), H/L = hi/lo bf16x2 planes.
// SPLITS=1: plain tf32, H/L = even-k / odd-k tf32 planes (2x mma8 per chunk).
struct GemmP {
    const float* A; long long a_sm, a_sk, a_b;
    const float* Bm; long long b_sk, b_sn, b_b;
    float* C; long long c_row, c_b;
    const float* bias; int bias_per_m;
    int M, N, K, mode;           // mode: 0 plain, 1 enc-out (pad zero + combined), 2 (+emb)*R2
    const int* tokens;
    const float* emb; long long emb_b;
    float* C2;
};

__device__ __forceinline__ unsigned f2tf(float x) {
    unsigned r;
    asm("cvt.rna.tf32.f32 %0, %1;" : "=r"(r) : "f"(x));
    return r;
}

__device__ __forceinline__ void cvt_pair(float x0, float x1, unsigned& hw, unsigned& lw) {
    __nv_bfloat162 h = __floats2bfloat162_rn(x0, x1);
    float2 hf = __bfloat1622float2(h);
    __nv_bfloat162 l = __floats2bfloat162_rn(x0 - hf.x, x1 - hf.y);
    hw = *reinterpret_cast<unsigned*>(&h);
    lw = *reinterpret_cast<unsigned*>(&l);
}

__device__ __forceinline__ void mma16(float* d, const unsigned* a, const unsigned* b) {
    asm volatile(
        "mma.sync.aligned.m16n8k16.row.col.f32.bf16.bf16.f32 "
        "{%0,%1,%2,%3}, {%4,%5,%6,%7}, {%8,%9}, {%0,%1,%2,%3};"
        : "+f"(d[0]), "+f"(d[1]), "+f"(d[2]), "+f"(d[3])
        : "r"(a[0]), "r"(a[1]), "r"(a[2]), "r"(a[3]), "r"(b[0]), "r"(b[1]));
}

__device__ __forceinline__ void mma8(float* d, const unsigned* a, const unsigned* b) {
    asm volatile(
        "mma.sync.aligned.m16n8k8.row.col.f32.tf32.tf32.f32 "
        "{%0,%1,%2,%3}, {%4,%5,%6,%7}, {%8,%9}, {%0,%1,%2,%3};"
        : "+f"(d[0]), "+f"(d[1]), "+f"(d[2]), "+f"(d[3])
        : "r"(a[0]), "r"(a[1]), "r"(a[2]), "r"(a[3]), "r"(b[0]), "r"(b[1]));
}

// encode pair (x0 = even k, x1 = odd k) into the two planes
template <int SPLITS>
__device__ __forceinline__ void enc_pair(float x0, float x1, unsigned& hw, unsigned& lw) {
    if (SPLITS == 3) cvt_pair(x0, x1, hw, lw);
    else { hw = f2tf(x0); lw = f2tf(x1); }
}

// ---- A tile: 128(m) x 32(k) into 16 regs ----
__device__ __forceinline__ void load_tileA(const GemmP& p, long long base, int m0, int k0,
                                           int tid, float* r) {
    if (p.a_sk == 1) {
        int mm = tid >> 1, kb = (tid & 1) << 4;
        const float* q = p.A + base + (long long)(m0 + mm) * p.a_sm + k0 + kb;
#pragma unroll
        for (int u = 0; u < 4; u++) {
            float4 v = *(const float4*)(q + u * 4);
            r[u * 4 + 0] = v.x; r[u * 4 + 1] = v.y; r[u * 4 + 2] = v.z; r[u * 4 + 3] = v.w;
        }
    } else {
#pragma unroll
        for (int q = 0; q < 8; q++) {
            int j = tid + q * 256;
            int mm = j & 127, k2 = j >> 7;
            long long b2 = base + (long long)(m0 + mm) * p.a_sm;
            r[q * 2]     = p.A[b2 + (long long)(k0 + 2 * k2) * p.a_sk];
            r[q * 2 + 1] = p.A[b2 + (long long)(k0 + 2 * k2 + 1) * p.a_sk];
        }
    }
}

template <int SPLITS>
__device__ __forceinline__ void sts_tileA(unsigned (*H)[136], unsigned (*L)[136],
                                          bool contig, int tid, const float* r) {
    if (contig) {
        int mm = tid >> 1, kb2 = (tid & 1) << 3;
#pragma unroll
        for (int u = 0; u < 8; u++)
            enc_pair<SPLITS>(r[u * 2], r[u * 2 + 1], H[kb2 + u][mm], L[kb2 + u][mm]);
    } else {
#pragma unroll
        for (int q = 0; q < 8; q++) {
            int j = tid + q * 256;
            int mm = j & 127, k2 = j >> 7;
            enc_pair<SPLITS>(r[q * 2], r[q * 2 + 1], H[k2][mm], L[k2][mm]);
        }
    }
}

// ---- B tile: 64(n) x 32(k) into 8 regs ----
__device__ __forceinline__ void load_tileB(const GemmP& p, long long base, int n0, int k0,
                                           int tid, float* r) {
    if (p.b_sk == 1) {
        int nn = tid >> 2, kb = (tid & 3) << 3;
        const float* q = p.Bm + base + (long long)(n0 + nn) * p.b_sn + k0 + kb;
#pragma unroll
        for (int u = 0; u < 2; u++) {
            float4 v = *(const float4*)(q + u * 4);
            r[u * 4 + 0] = v.x; r[u * 4 + 1] = v.y; r[u * 4 + 2] = v.z; r[u * 4 + 3] = v.w;
        }
    } else {
#pragma unroll
        for (int q = 0; q < 4; q++) {
            int j = tid + q * 256;
            int nn = j & 63, k2 = j >> 6;
            long long b2 = base + (long long)(n0 + nn) * p.b_sn;
            r[q * 2]     = p.Bm[b2 + (long long)(k0 + 2 * k2) * p.b_sk];
            r[q * 2 + 1] = p.Bm[b2 + (long long)(k0 + 2 * k2 + 1) * p.b_sk];
        }
    }
}

template <int SPLITS>
__device__ __forceinline__ void sts_tileB(unsigned (*H)[72], unsigned (*L)[72],
                                          bool contig, int tid, const float* r) {
    if (contig) {
        int nn = tid >> 2, kb2 = (tid & 3) << 2;  // k2 rows kb2..kb2+3
#pragma unroll
        for (int u = 0; u < 4; u++)
            enc_pair<SPLITS>(r[u * 2], r[u * 2 + 1], H[kb2 + u][nn], L[kb2 + u][nn]);
    } else {
#pragma unroll
        for (int q = 0; q < 4; q++) {
            int j = tid + q * 256;
            int nn = j & 63, k2 = j >> 6;
            enc_pair<SPLITS>(r[q * 2], r[q * 2 + 1], H[k2][nn], L[k2][nn]);
        }
    }
}

template <int SPLITS>
__global__ __launch_bounds__(256, 2) void tgemm_kernel(GemmP p) {
    __shared__ unsigned Ah[16][136], Al[16][136];
    __shared__ unsigned Bh[16][72], Bl[16][72];
    int bz = blockIdx.z;
    long long Abase = (long long)bz * p.a_b;
    long long Bbase = (long long)bz * p.b_b;
    int m0 = blockIdx.y * 128, n0 = blockIdx.x * 64;
    int tid = threadIdx.x;
    int warp = tid >> 5, lane = tid & 31;
    int wm = warp >> 1, wn = warp & 1;   // 4x2 warps; warp tile 32(m) x 32(n)
    int tig = lane & 3, grp = lane >> 2;
    bool acontig = (p.a_sk == 1);
    bool bcontig = (p.b_sk == 1);

    float acc[2][4][4];
#pragma unroll
    for (int i = 0; i < 2; i++)
#pragma unroll
        for (int j = 0; j < 4; j++)
#pragma unroll
            for (int r = 0; r < 4; r++) acc[i][j][r] = 0.f;

    float regA[16], regB[8];
    int T = p.K / 32;
    load_tileA(p, Abase, m0, 0, tid, regA);
    load_tileB(p, Bbase, n0, 0, tid, regB);

    for (int t = 0; t < T; t++) {
        sts_tileA<SPLITS>(Ah, Al, acontig, tid, regA);
        sts_tileB<SPLITS>(Bh, Bl, bcontig, tid, regB);
        __syncthreads();
        if (t + 1 < T) {  // prefetch; LDG latency hides behind MMA block below
            load_tileA(p, Abase, m0, (t + 1) * 32, tid, regA);
            load_tileB(p, Bbase, n0, (t + 1) * 32, tid, regB);
        }
#pragma unroll
        for (int kc2 = 0; kc2 < 16; kc2 += 8) {
            unsigned ah[2][4], al[2][4], bh[4][2], bl[4][2];
#pragma unroll
            for (int mf = 0; mf < 2; mf++) {
                int mr = wm * 32 + mf * 16 + grp;
                ah[mf][0] = Ah[kc2 + tig][mr];
                ah[mf][1] = Ah[kc2 + tig][mr + 8];
                ah[mf][2] = Ah[kc2 + tig + 4][mr];
                ah[mf][3] = Ah[kc2 + tig + 4][mr + 8];
                al[mf][0] = Al[kc2 + tig][mr];
                al[mf][1] = Al[kc2 + tig][mr + 8];
                al[mf][2] = Al[kc2 + tig + 4][mr];
                al[mf][3] = Al[kc2 + tig + 4][mr + 8];
            }
#pragma unroll
            for (int nf = 0; nf < 4; nf++) {
                int nc = wn * 32 + nf * 8 + grp;
                bh[nf][0] = Bh[kc2 + tig][nc];
                bh[nf][1] = Bh[kc2 + tig + 4][nc];
                bl[nf][0] = Bl[kc2 + tig][nc];
                bl[nf][1] = Bl[kc2 + tig + 4][nc];
            }
#pragma unroll
            for (int mf = 0; mf < 2; mf++)
#pragma unroll
                for (int nf = 0; nf < 4; nf++) {
                    if (SPLITS == 3) {
                        mma16(acc[mf][nf], ah[mf], bh[nf]);
                        mma16(acc[mf][nf], ah[mf], bl[nf]);
                        mma16(acc[mf][nf], al[mf], bh[nf]);
                    } else {
                        mma8(acc[mf][nf], ah[mf], bh[nf]);  // even k
                        mma8(acc[mf][nf], al[mf], bl[nf]);  // odd k
                    }
                }
        }
        __syncthreads();
    }

    // ---- epilogue ----
#pragma unroll
    for (int mf = 0; mf < 2; mf++) {
#pragma unroll
        for (int nf = 0; nf < 4; nf++) {
#pragma unroll
            for (int half = 0; half < 2; half++) {
                int m = m0 + wm * 32 + mf * 16 + grp + half * 8;
                int n = n0 + wn * 32 + nf * 8 + tig * 2;
                float v0 = acc[mf][nf][half * 2 + 0];
                float v1 = acc[mf][nf][half * 2 + 1];
                if (p.bias) {
                    if (p.bias_per_m) { float bm = p.bias[m]; v0 += bm; v1 += bm; }
                    else { v0 += p.bias[n]; v1 += p.bias[n + 1]; }
                }
                long long cidx = (long long)bz * p.c_b + (long long)m * p.c_row + n;
                if (p.mode == 0) {
                    *(float2*)&p.C[cidx] = make_float2(v0, v1);
                } else if (p.mode == 1) {
                    int tok = p.tokens[bz * SSQ + m];
                    if (tok == 0) { v0 = 0.f; v1 = 0.f; }
                    *(float2*)&p.C[cidx] = make_float2(v0, v1);
                    float2 e = *(const float2*)&p.emb[(long long)bz * p.emb_b + (long long)m * p.N + n];
                    *(float2*)&p.C2[cidx] = make_float2((v0 + e.x) * R2F, (v1 + e.y) * R2F);
                } else {
                    float2 e = *(const float2*)&p.emb[(long long)bz * p.emb_b + (long long)m * p.N + n];
                    *(float2*)&p.C[cidx] = make_float2((v0 + e.x) * R2F, (v1 + e.y) * R2F);
                }
            }
        }
    }
}

// ---------------- vocab GEMM: 1x tf32, pipelined (R7-proven) ----------------
__global__ __launch_bounds__(256) void vgemm_kernel(const float* __restrict__ A,
                                                    const float* __restrict__ W,
                                                    const float* __restrict__ bias,
                                                    float* __restrict__ C) {
    __shared__ unsigned At[32][136], Bt[32][136];
    int m0 = blockIdx.y * 128, n0 = blockIdx.x * 128;
    int tid = threadIdx.x;
    int warp = tid >> 5, lane = tid & 31;
    int wm = warp >> 2, wn = warp & 3;
    int tig = lane & 3, grp = lane >> 2;

    float acc[4][4][4];
#pragma unroll
    for (int i = 0; i < 4; i++)
#pragma unroll
        for (int j = 0; j < 4; j++)
#pragma unroll
            for (int r = 0; r < 4; r++) acc[i][j][r] = 0.f;

    int am = tid >> 1, akb = (tid & 1) << 4;
    float regA[16], regB[16];

    const float* Ap0 = A + (long long)(m0 + am) * DDQ + akb;
#pragma unroll
    for (int u = 0; u < 4; u++) {
        float4 v = *(const float4*)(Ap0 + u * 4);
        regA[u * 4 + 0] = v.x; regA[u * 4 + 1] = v.y; regA[u * 4 + 2] = v.z; regA[u * 4 + 3] = v.w;
    }
#pragma unroll
    for (int q = 0; q < 16; q++) {
        int j = tid + q * 256;
        int nn = j & 127, kk = j >> 7;
        regB[q] = W[(long long)kk * VVQ + n0 + nn];
    }

    int T = DDQ / 32;  // 16
    for (int t = 0; t < T; t++) {
#pragma unroll
        for (int u = 0; u < 16; u++) At[akb + u][am] = f2tf(regA[u]);
#pragma unroll
        for (int q = 0; q < 16; q++) {
            int j = tid + q * 256;
            int nn = j & 127, kk = j >> 7;
            Bt[kk][nn] = f2tf(regB[q]);
        }
        __syncthreads();
        if (t + 1 < T) {
            int k0 = (t + 1) * 32;
            const float* Ap = A + (long long)(m0 + am) * DDQ + k0 + akb;
#pragma unroll
            for (int u = 0; u < 4; u++) {
                float4 v = *(const float4*)(Ap + u * 4);
                regA[u * 4 + 0] = v.x; regA[u * 4 + 1] = v.y; regA[u * 4 + 2] = v.z; regA[u * 4 + 3] = v.w;
            }
#pragma unroll
            for (int q = 0; q < 16; q++) {
                int j = tid + q * 256;
                int nn = j & 127, kk = j >> 7;
                regB[q] = W[(long long)(k0 + kk) * VVQ + n0 + nn];
            }
        }
#pragma unroll
        for (int ks = 0; ks < 32; ks += 8) {
            unsigned af[4][4], bf[4][2];
#pragma unroll
            for (int mf = 0; mf < 4; mf++) {
                int mr = wm * 64 + mf * 16 + grp;
                af[mf][0] = At[ks + tig][mr];
                af[mf][1] = At[ks + tig][mr + 8];
                af[mf][2] = At[ks + tig + 4][mr];
                af[mf][3] = At[ks + tig + 4][mr + 8];
            }
#pragma unroll
            for (int nf = 0; nf < 4; nf++) {
                int nc = wn * 32 + nf * 8 + grp;
                bf[nf][0] = Bt[ks + tig][nc];
                bf[nf][1] = Bt[ks + tig + 4][nc];
            }
#pragma unroll
            for (int mf = 0; mf < 4; mf++)
#pragma unroll
                for (int nf = 0; nf < 4; nf++) mma8(acc[mf][nf], af[mf], bf[nf]);
        }
        __syncthreads();
    }

#pragma unroll
    for (int mf = 0; mf < 4; mf++)
#pragma unroll
        for (int nf = 0; nf < 4; nf++)
#pragma unroll
            for (int half = 0; half < 2; half++) {
                int m = m0 + wm * 64 + mf * 16 + grp + half * 8;
                int n = n0 + wn * 32 + nf * 8 + tig * 2;
                float v0 = acc[mf][nf][half * 2 + 0] + bias[n];
                float v1 = acc[mf][nf][half * 2 + 1] + bias[n + 1];
                *(float2*)&C[(long long)m * VVQ + n] = make_float2(v0, v1);
            }
}

// ---------------- embeddings ----------------
__global__ void embed_kernel(const int* __restrict__ tokens, const float* __restrict__ tok_emb,
                             const float* __restrict__ pos_emb, float* __restrict__ out, int Slen) {
    int b = blockIdx.y;
    __shared__ int pos[SSQ];
    if (threadIdx.x == 0) {
        int c = 0;
        for (int s = 0; s < Slen; s++) {
            int m = (tokens[b * Slen + s] != 0) ? 1 : 0;
            c += m;
            pos[s] = c * m;
        }
    }
    __syncthreads();
    int chunk = Slen / gridDim.x;
    int s0 = blockIdx.x * chunk;
    for (int idx = threadIdx.x; idx < chunk * DDQ; idx += blockDim.x) {
        int s = s0 + idx / DDQ;
        int d = idx % DDQ;
        int tk = tokens[b * Slen + s];
        out[((long long)b * Slen + s) * DDQ + d] =
            tok_emb[(long long)tk * DDQ + d] + pos_emb[(long long)pos[s] * DDQ + d];
    }
}

// ---------------- im2col, cheap (r, b) grid indexing ----------------
__global__ void im2col_enc_kernel(const float* __restrict__ x, const int* __restrict__ tokens,
                                  float* __restrict__ out) {
    int r = blockIdx.x;        // 0..3*DDQ-1, r = ic*3 + k
    int b = blockIdx.y;
    int s = threadIdx.x;       // 0..SSQ-1
    int ic = r / 3, k = r - ic * 3;
    int s2 = s + k - 1;
    float v = 0.f;
    if (s2 >= 0 && s2 < SSQ && tokens[b * SSQ + s2] != 0)
        v = x[((long long)b * DDQ + ic) * SSQ + s2];
    out[((long long)b * 3 * DDQ + r) * SSQ + s] = v;
}

__global__ void im2col_dec_kernel(const float* __restrict__ x, float* __restrict__ out) {
    int r = blockIdx.x;
    int b = blockIdx.y;
    int t = threadIdx.x;       // 0..TTQ-1
    int ic = r / 3, k = r - ic * 3;
    int t2 = t + k - 2;        // causal: pad K-1=2 left
    float v = (t2 >= 0) ? x[((long long)b * DDQ + ic) * TTQ + t2] : 0.f;
    out[((long long)b * 3 * DDQ + r) * TTQ + t] = v;
}

// ---------------- GLU (+ optional residual), float4 ----------------
__global__ void glu_res_kernel(const float* __restrict__ y, float* __restrict__ x,
                               int total4, int DS4, int apply_res) {
    int i = blockIdx.x * blockDim.x + threadIdx.x;
    if (i >= total4) return;
    int b = i / DS4;
    int rem = i - b * DS4;
    float4 a = ((const float4*)y)[(long long)b * 2 * DS4 + rem];
    float4 g = ((const float4*)y)[(long long)b * 2 * DS4 + DS4 + rem];
    float4 v;
    v.x = a.x / (1.f + expf(-g.x));
    v.y = a.y / (1.f + expf(-g.y));
    v.z = a.z / (1.f + expf(-g.z));
    v.w = a.w / (1.f + expf(-g.w));
    if (apply_res) {
        float4 xv = ((float4*)x)[i];
        v.x = (v.x + xv.x) * R2F; v.y = (v.y + xv.y) * R2F;
        v.z = (v.z + xv.z) * R2F; v.w = (v.w + xv.w) * R2F;
    }
    ((float4*)x)[i] = v;
}

// ---------------- decoder combine: x = ((c + att2^T)*R2 + x)*R2, (ch,b) grid ----
__global__ void dec_combine_kernel(float* __restrict__ x, const float* __restrict__ c,
                                   const float* __restrict__ att2) {
    int ch = blockIdx.x;
    int b = blockIdx.y;
    int t = threadIdx.x;       // 0..TTQ-1
    long long idx = ((long long)b * DDQ + ch) * TTQ + t;
    float cc = (c[idx] + att2[((long long)b * TTQ + t) * DDQ + ch]) * R2F;
    x[idx] = (cc + x[idx]) * R2F;
}

// ---------------- masked softmax over S ----------------
__global__ void softmax_mask_kernel(float* __restrict__ energy, const int* __restrict__ src) {
    int row = blockIdx.x;           // b*T + t
    int b = row / TTQ;
    float* e = energy + (long long)row * SSQ;
    int s = threadIdx.x;            // 256 = S
    float v = (src[b * SSQ + s] == 0) ? -INFINITY : e[s];
    __shared__ float red[SSQ];
    red[s] = v;
    __syncthreads();
    for (int off = 128; off > 0; off >>= 1) {
        if (s < off) red[s] = fmaxf(red[s], red[s + off]);
        __syncthreads();
    }
    float mx = red[0];
    __syncthreads();
    float ex = expf(v - mx);
    red[s] = ex;
    __syncthreads();
    for (int off = 128; off > 0; off >>= 1) {
        if (s < off) red[s] += red[s + off];
        __syncthreads();
    }
    e[s] = ex / red[0];
}

// ---------------- host side ----------------
static void gemm(const float* A, long long a_sm, long long a_sk, long long a_b,
                 const float* Bm, long long b_sk, long long b_sn, long long b_b,
                 float* C, long long c_row, long long c_b,
                 const float* bias, int bias_per_m,
                 int M, int N, int K, int nb,
                 int mode = 0, const int* tokens = nullptr,
                 const float* emb = nullptr, long long emb_b = 0, float* C2 = nullptr,
                 int splits = 3) {
    GemmP p;
    p.A = A; p.a_sm = a_sm; p.a_sk = a_sk; p.a_b = a_b;
    p.Bm = Bm; p.b_sk = b_sk; p.b_sn = b_sn; p.b_b = b_b;
    p.C = C; p.c_row = c_row; p.c_b = c_b;
    p.bias = bias; p.bias_per_m = bias_per_m;
    p.M = M; p.N = N; p.K = K; p.mode = mode;
    p.tokens = tokens; p.emb = emb; p.emb_b = emb_b; p.C2 = C2;
    dim3 grid(N / 64, M / 128, nb);
    if (splits == 3) tgemm_kernel<3><<<grid, 256>>>(p);
    else             tgemm_kernel<1><<<grid, 256>>>(p);
}

extern "C" void kernel_launch(void* const* d_in, const int* in_sizes, int n_in,
                              void* d_out, int out_size) {
    const int*   src        = (const int*)d_in[0];
    const int*   trg        = (const int*)d_in[1];
    const float* enc_tok    = (const float*)d_in[2];
    const float* enc_pos    = (const float*)d_in[3];
    const float* dec_tok    = (const float*)d_in[4];
    const float* dec_pos    = (const float*)d_in[5];
    const float* enc_in_w   = (const float*)d_in[6];
    const float* enc_in_b   = (const float*)d_in[7];
    const float* enc_conv_w = (const float*)d_in[8];
    const float* enc_conv_b = (const float*)d_in[9];
    const float* enc_out_w  = (const float*)d_in[10];
    const float* enc_out_b  = (const float*)d_in[11];
    const float* dec_in_w   = (const float*)d_in[12];
    const float* dec_in_b   = (const float*)d_in[13];
    const float* dec_conv_w = (const float*)d_in[14];
    const float* dec_conv_b = (const float*)d_in[15];
    const float* attn_in_w  = (const float*)d_in[16];
    const float* attn_in_b  = (const float*)d_in[17];
    const float* attn_out_w = (const float*)d_in[18];
    const float* attn_out_b = (const float*)d_in[19];
    const float* dec_out_w  = (const float*)d_in[20];
    const float* dec_out_b  = (const float*)d_in[21];
    const float* vocab_w    = (const float*)d_in[22];
    const float* vocab_b    = (const float*)d_in[23];
    float* logits = (float*)d_out;

    void* sp;
    cudaGetSymbolAddress(&sp, g_scratch);
    float* base = (float*)sp;
    float* enc_emb    = base;
    float* enc_x      = base + 2097152;
    float* im2col     = base + 4194304;
    float* ybuf       = base + 10485760;
    float* enc_conved = base + 14680064;
    float* enc_comb   = base + 16777216;
    float* dec_emb    = base + 18874368;
    float* dec_x      = base + 19922944;
    float* dec_c      = base + 20971520;
    float* qbuf       = base + 22020096;
    float* energy     = base + 23068672;
    float* att        = base + 23592960;
    float* att2       = base + 24641536;

    // ---- embeddings ----
    embed_kernel<<<dim3(4, BB), 256>>>(src, enc_tok, enc_pos, enc_emb, SSQ);
    embed_kernel<<<dim3(4, BB), 256>>>(trg, dec_tok, dec_pos, dec_emb, TTQ);

    // ---- encoder in-projection -> x[b][c][s] ----
    gemm(enc_in_w, 1, DDQ, 0,
         enc_emb, 1, DDQ, (long long)SSQ * DDQ,
         enc_x, SSQ, (long long)DDQ * SSQ,
         enc_in_b, 1, DDQ, SSQ, DDQ, BB);

    // ---- encoder conv stack ----
    for (int l = 0; l < LLQ; l++) {
        im2col_enc_kernel<<<dim3(3 * DDQ, BB), SSQ>>>(enc_x, src, im2col);
        gemm(enc_conv_w + (long long)l * 2 * DDQ * DDQ * 3, 3 * DDQ, 1, 0,
             im2col, SSQ, 1, (long long)3 * DDQ * SSQ,
             ybuf, SSQ, (long long)2 * DDQ * SSQ,
             enc_conv_b + l * 2 * DDQ, 1, 2 * DDQ, SSQ, 3 * DDQ, BB);
        int tot4 = BB * DDQ * SSQ / 4;
        glu_res_kernel<<<(tot4 + 255) / 256, 256>>>(ybuf, enc_x, tot4, DDQ * SSQ / 4, 1);
    }

    // ---- encoder out-projection (+pad mask, combined) ----
    gemm(enc_x, 1, SSQ, (long long)DDQ * SSQ,
         enc_out_w, DDQ, 1, 0,
         enc_conved, DDQ, (long long)SSQ * DDQ,
         enc_out_b, 0, SSQ, DDQ, DDQ, BB,
         1, src, enc_emb, (long long)SSQ * DDQ, enc_comb);

    // ---- decoder in-projection -> x[b][c][t] ----
    gemm(dec_in_w, 1, DDQ, 0,
         dec_emb, 1, DDQ, (long long)TTQ * DDQ,
         dec_x, TTQ, (long long)DDQ * TTQ,
         dec_in_b, 1, DDQ, TTQ, DDQ, BB);

    // ---- decoder layers ----
    for (int l = 0; l < LLQ; l++) {
        im2col_dec_kernel<<<dim3(3 * DDQ, BB), TTQ>>>(dec_x, im2col);
        gemm(dec_conv_w + (long long)l * 2 * DDQ * DDQ * 3, 3 * DDQ, 1, 0,
             im2col, TTQ, 1, (long long)3 * DDQ * TTQ,
             ybuf, TTQ, (long long)2 * DDQ * TTQ,
             dec_conv_b + l * 2 * DDQ, 1, 2 * DDQ, TTQ, 3 * DDQ, BB);
        int tot4 = BB * DDQ * TTQ / 4;
        glu_res_kernel<<<(tot4 + 255) / 256, 256>>>(ybuf, dec_c, tot4, DDQ * TTQ / 4, 0);

        // q = (c^T @ Wq + bq + emb) * R2   [tf32 1x]
        gemm(dec_c, 1, TTQ, (long long)DDQ * TTQ,
             attn_in_w + (long long)l * DDQ * DDQ, DDQ, 1, 0,
             qbuf, DDQ, (long long)TTQ * DDQ,
             attn_in_b + l * DDQ, 0, TTQ, DDQ, DDQ, BB,
             2, nullptr, dec_emb, (long long)TTQ * DDQ, nullptr, 1);

        // energy = q @ enc_conved^T   [tf32 1x]
        gemm(qbuf, DDQ, 1, (long long)TTQ * DDQ,
             enc_conved, 1, DDQ, (long long)SSQ * DDQ,
             energy, SSQ, (long long)TTQ * SSQ,
             nullptr, 0, TTQ, SSQ, DDQ, BB,
             0, nullptr, nullptr, 0, nullptr, 1);

        softmax_mask_kernel<<<BB * TTQ, SSQ>>>(energy, src);

        // att = attn @ enc_combined   [tf32 1x]
        gemm(energy, SSQ, 1, (long long)TTQ * SSQ,
             enc_comb, DDQ, 1, (long long)SSQ * DDQ,
             att, DDQ, (long long)TTQ * DDQ,
             nullptr, 0, TTQ, DDQ, SSQ, BB,
             0, nullptr, nullptr, 0, nullptr, 1);

        // att2 = att @ Wout + bout   [tf32 1x]
        gemm(att, DDQ, 1, 0,
             attn_out_w + (long long)l * DDQ * DDQ, DDQ, 1, 0,
             att2, DDQ, 0,
             attn_out_b + l * DDQ, 0, BB * TTQ, DDQ, DDQ, 1,
             0, nullptr, nullptr, 0, nullptr, 1);

        dec_combine_kernel<<<dim3(DDQ, BB), TTQ>>>(dec_x, dec_c, att2);
    }

    // ---- decoder out-projection -> [B,T,D] (reuse qbuf) ----
    gemm(dec_x, 1, TTQ, (long long)DDQ * TTQ,
         dec_out_w, DDQ, 1, 0,
         qbuf, DDQ, (long long)TTQ * DDQ,
         dec_out_b, 0, TTQ, DDQ, DDQ, BB);

    // ---- vocab projection -> logits [B*T, V] ----
    vgemm_kernel<<<dim3(VVQ / 128, (BB * TTQ) / 128), 256>>>(qbuf, vocab_w, vocab_b, logits);
}

// round 14
// speedup vs baseline: 1.1396x; 1.0278x over previous
#include <cuda_runtime.h>
#include <cuda_bf16.h>
#include <math.h>

#define BB 16
#define SSQ 256
#define TTQ 128
#define DDQ 512
#define VVQ 32000
#define LLQ 3
#define R2F 0.70710678118654752440f

// ---------------- scratch (single __device__ array, no allocs) ----------------
__device__ float g_scratch[25690112];

// ---------------- tensor-core batched GEMM (128x64 tile, 2 CTAs/SM) --------------
// SPLITS=3: bf16 split-pair (fp32-class accuracy), H/L = hi/lo bf16x2 planes.
// SPLITS=1: plain tf32, H/L = even-k / odd-k tf32 planes (2x mma8 per chunk).
struct GemmP {
    const float* A; long long a_sm, a_sk, a_b;
    const float* Bm; long long b_sk, b_sn, b_b;
    float* C; long long c_row, c_b;
    const float* bias; int bias_per_m;
    int M, N, K, mode;           // mode: 0 plain, 1 enc-out (pad zero + combined), 2 (+emb)*R2
    const int* tokens;
    const float* emb; long long emb_b;
    float* C2;
};

__device__ __forceinline__ unsigned f2tf(float x) {
    unsigned r;
    asm("cvt.rna.tf32.f32 %0, %1;" : "=r"(r) : "f"(x));
    return r;
}

__device__ __forceinline__ void cvt_pair(float x0, float x1, unsigned& hw, unsigned& lw) {
    __nv_bfloat162 h = __floats2bfloat162_rn(x0, x1);
    float2 hf = __bfloat1622float2(h);
    __nv_bfloat162 l = __floats2bfloat162_rn(x0 - hf.x, x1 - hf.y);
    hw = *reinterpret_cast<unsigned*>(&h);
    lw = *reinterpret_cast<unsigned*>(&l);
}

__device__ __forceinline__ void mma16(float* d, const unsigned* a, const unsigned* b) {
    asm volatile(
        "mma.sync.aligned.m16n8k16.row.col.f32.bf16.bf16.f32 "
        "{%0,%1,%2,%3}, {%4,%5,%6,%7}, {%8,%9}, {%0,%1,%2,%3};"
        : "+f"(d[0]), "+f"(d[1]), "+f"(d[2]), "+f"(d[3])
        : "r"(a[0]), "r"(a[1]), "r"(a[2]), "r"(a[3]), "r"(b[0]), "r"(b[1]));
}

__device__ __forceinline__ void mma8(float* d, const unsigned* a, const unsigned* b) {
    asm volatile(
        "mma.sync.aligned.m16n8k8.row.col.f32.tf32.tf32.f32 "
        "{%0,%1,%2,%3}, {%4,%5,%6,%7}, {%8,%9}, {%0,%1,%2,%3};"
        : "+f"(d[0]), "+f"(d[1]), "+f"(d[2]), "+f"(d[3])
        : "r"(a[0]), "r"(a[1]), "r"(a[2]), "r"(a[3]), "r"(b[0]), "r"(b[1]));
}

// encode pair (x0 = even k, x1 = odd k) into the two planes
template <int SPLITS>
__device__ __forceinline__ void enc_pair(float x0, float x1, unsigned& hw, unsigned& lw) {
    if (SPLITS == 3) cvt_pair(x0, x1, hw, lw);
    else { hw = f2tf(x0); lw = f2tf(x1); }
}

// ---- A tile: 128(m) x 32(k) into 16 regs ----
__device__ __forceinline__ void load_tileA(const GemmP& p, long long base, int m0, int k0,
                                           int tid, float* r) {
    if (p.a_sk == 1) {
        int mm = tid >> 1, kb = (tid & 1) << 4;
        const float* q = p.A + base + (long long)(m0 + mm) * p.a_sm + k0 + kb;
#pragma unroll
        for (int u = 0; u < 4; u++) {
            float4 v = *(const float4*)(q + u * 4);
            r[u * 4 + 0] = v.x; r[u * 4 + 1] = v.y; r[u * 4 + 2] = v.z; r[u * 4 + 3] = v.w;
        }
    } else {
#pragma unroll
        for (int q = 0; q < 8; q++) {
            int j = tid + q * 256;
            int mm = j & 127, k2 = j >> 7;
            long long b2 = base + (long long)(m0 + mm) * p.a_sm;
            r[q * 2]     = p.A[b2 + (long long)(k0 + 2 * k2) * p.a_sk];
            r[q * 2 + 1] = p.A[b2 + (long long)(k0 + 2 * k2 + 1) * p.a_sk];
        }
    }
}

template <int SPLITS>
__device__ __forceinline__ void sts_tileA(unsigned (*H)[136], unsigned (*L)[136],
                                          bool contig, int tid, const float* r) {
    if (contig) {
        int mm = tid >> 1, kb2 = (tid & 1) << 3;
#pragma unroll
        for (int u = 0; u < 8; u++)
            enc_pair<SPLITS>(r[u * 2], r[u * 2 + 1], H[kb2 + u][mm], L[kb2 + u][mm]);
    } else {
#pragma unroll
        for (int q = 0; q < 8; q++) {
            int j = tid + q * 256;
            int mm = j & 127, k2 = j >> 7;
            enc_pair<SPLITS>(r[q * 2], r[q * 2 + 1], H[k2][mm], L[k2][mm]);
        }
    }
}

// ---- B tile: 64(n) x 32(k) into 8 regs ----
__device__ __forceinline__ void load_tileB(const GemmP& p, long long base, int n0, int k0,
                                           int tid, float* r) {
    if (p.b_sk == 1) {
        int nn = tid >> 2, kb = (tid & 3) << 3;
        const float* q = p.Bm + base + (long long)(n0 + nn) * p.b_sn + k0 + kb;
#pragma unroll
        for (int u = 0; u < 2; u++) {
            float4 v = *(const float4*)(q + u * 4);
            r[u * 4 + 0] = v.x; r[u * 4 + 1] = v.y; r[u * 4 + 2] = v.z; r[u * 4 + 3] = v.w;
        }
    } else {
#pragma unroll
        for (int q = 0; q < 4; q++) {
            int j = tid + q * 256;
            int nn = j & 63, k2 = j >> 6;
            long long b2 = base + (long long)(n0 + nn) * p.b_sn;
            r[q * 2]     = p.Bm[b2 + (long long)(k0 + 2 * k2) * p.b_sk];
            r[q * 2 + 1] = p.Bm[b2 + (long long)(k0 + 2 * k2 + 1) * p.b_sk];
        }
    }
}

template <int SPLITS>
__device__ __forceinline__ void sts_tileB(unsigned (*H)[72], unsigned (*L)[72],
                                          bool contig, int tid, const float* r) {
    if (contig) {
        int nn = tid >> 2, kb2 = (tid & 3) << 2;  // k2 rows kb2..kb2+3
#pragma unroll
        for (int u = 0; u < 4; u++)
            enc_pair<SPLITS>(r[u * 2], r[u * 2 + 1], H[kb2 + u][nn], L[kb2 + u][nn]);
    } else {
#pragma unroll
        for (int q = 0; q < 4; q++) {
            int j = tid + q * 256;
            int nn = j & 63, k2 = j >> 6;
            enc_pair<SPLITS>(r[q * 2], r[q * 2 + 1], H[k2][nn], L[k2][nn]);
        }
    }
}

template <int SPLITS>
__global__ __launch_bounds__(256, 2) void tgemm_kernel(GemmP p) {
    __shared__ unsigned Ah[16][136], Al[16][136];
    __shared__ unsigned Bh[16][72], Bl[16][72];
    int bz = blockIdx.z;
    long long Abase = (long long)bz * p.a_b;
    long long Bbase = (long long)bz * p.b_b;
    int m0 = blockIdx.y * 128, n0 = blockIdx.x * 64;
    int tid = threadIdx.x;
    int warp = tid >> 5, lane = tid & 31;
    int wm = warp >> 1, wn = warp & 1;   // 4x2 warps; warp tile 32(m) x 32(n)
    int tig = lane & 3, grp = lane >> 2;
    bool acontig = (p.a_sk == 1);
    bool bcontig = (p.b_sk == 1);

    float acc[2][4][4];
#pragma unroll
    for (int i = 0; i < 2; i++)
#pragma unroll
        for (int j = 0; j < 4; j++)
#pragma unroll
            for (int r = 0; r < 4; r++) acc[i][j][r] = 0.f;

    float regA[16], regB[8];
    int T = p.K / 32;
    load_tileA(p, Abase, m0, 0, tid, regA);
    load_tileB(p, Bbase, n0, 0, tid, regB);

    for (int t = 0; t < T; t++) {
        sts_tileA<SPLITS>(Ah, Al, acontig, tid, regA);
        sts_tileB<SPLITS>(Bh, Bl, bcontig, tid, regB);
        __syncthreads();
        if (t + 1 < T) {  // prefetch; LDG latency hides behind MMA block below
            load_tileA(p, Abase, m0, (t + 1) * 32, tid, regA);
            load_tileB(p, Bbase, n0, (t + 1) * 32, tid, regB);
        }
#pragma unroll
        for (int kc2 = 0; kc2 < 16; kc2 += 8) {
            unsigned ah[2][4], al[2][4], bh[4][2], bl[4][2];
#pragma unroll
            for (int mf = 0; mf < 2; mf++) {
                int mr = wm * 32 + mf * 16 + grp;
                ah[mf][0] = Ah[kc2 + tig][mr];
                ah[mf][1] = Ah[kc2 + tig][mr + 8];
                ah[mf][2] = Ah[kc2 + tig + 4][mr];
                ah[mf][3] = Ah[kc2 + tig + 4][mr + 8];
                al[mf][0] = Al[kc2 + tig][mr];
                al[mf][1] = Al[kc2 + tig][mr + 8];
                al[mf][2] = Al[kc2 + tig + 4][mr];
                al[mf][3] = Al[kc2 + tig + 4][mr + 8];
            }
#pragma unroll
            for (int nf = 0; nf < 4; nf++) {
                int nc = wn * 32 + nf * 8 + grp;
                bh[nf][0] = Bh[kc2 + tig][nc];
                bh[nf][1] = Bh[kc2 + tig + 4][nc];
                bl[nf][0] = Bl[kc2 + tig][nc];
                bl[nf][1] = Bl[kc2 + tig + 4][nc];
            }
#pragma unroll
            for (int mf = 0; mf < 2; mf++)
#pragma unroll
                for (int nf = 0; nf < 4; nf++) {
                    if (SPLITS == 3) {
                        mma16(acc[mf][nf], ah[mf], bh[nf]);
                        mma16(acc[mf][nf], ah[mf], bl[nf]);
                        mma16(acc[mf][nf], al[mf], bh[nf]);
                    } else {
                        mma8(acc[mf][nf], ah[mf], bh[nf]);  // even k
                        mma8(acc[mf][nf], al[mf], bl[nf]);  // odd k
                    }
                }
        }
        __syncthreads();
    }

    // ---- epilogue ----
#pragma unroll
    for (int mf = 0; mf < 2; mf++) {
#pragma unroll
        for (int nf = 0; nf < 4; nf++) {
#pragma unroll
            for (int half = 0; half < 2; half++) {
                int m = m0 + wm * 32 + mf * 16 + grp + half * 8;
                int n = n0 + wn * 32 + nf * 8 + tig * 2;
                float v0 = acc[mf][nf][half * 2 + 0];
                float v1 = acc[mf][nf][half * 2 + 1];
                if (p.bias) {
                    if (p.bias_per_m) { float bm = p.bias[m]; v0 += bm; v1 += bm; }
                    else { v0 += p.bias[n]; v1 += p.bias[n + 1]; }
                }
                long long cidx = (long long)bz * p.c_b + (long long)m * p.c_row + n;
                if (p.mode == 0) {
                    *(float2*)&p.C[cidx] = make_float2(v0, v1);
                } else if (p.mode == 1) {
                    int tok = p.tokens[bz * SSQ + m];
                    if (tok == 0) { v0 = 0.f; v1 = 0.f; }
                    *(float2*)&p.C[cidx] = make_float2(v0, v1);
                    float2 e = *(const float2*)&p.emb[(long long)bz * p.emb_b + (long long)m * p.N + n];
                    *(float2*)&p.C2[cidx] = make_float2((v0 + e.x) * R2F, (v1 + e.y) * R2F);
                } else {
                    float2 e = *(const float2*)&p.emb[(long long)bz * p.emb_b + (long long)m * p.N + n];
                    *(float2*)&p.C[cidx] = make_float2((v0 + e.x) * R2F, (v1 + e.y) * R2F);
                }
            }
        }
    }
}

// ---------------- vocab GEMM: 1x tf32, pipelined (R7-proven) ----------------
__global__ __launch_bounds__(256) void vgemm_kernel(const float* __restrict__ A,
                                                    const float* __restrict__ W,
                                                    const float* __restrict__ bias,
                                                    float* __restrict__ C) {
    __shared__ unsigned At[32][136], Bt[32][136];
    int m0 = blockIdx.y * 128, n0 = blockIdx.x * 128;
    int tid = threadIdx.x;
    int warp = tid >> 5, lane = tid & 31;
    int wm = warp >> 2, wn = warp & 3;
    int tig = lane & 3, grp = lane >> 2;

    float acc[4][4][4];
#pragma unroll
    for (int i = 0; i < 4; i++)
#pragma unroll
        for (int j = 0; j < 4; j++)
#pragma unroll
            for (int r = 0; r < 4; r++) acc[i][j][r] = 0.f;

    int am = tid >> 1, akb = (tid & 1) << 4;
    float regA[16], regB[16];

    const float* Ap0 = A + (long long)(m0 + am) * DDQ + akb;
#pragma unroll
    for (int u = 0; u < 4; u++) {
        float4 v = *(const float4*)(Ap0 + u * 4);
        regA[u * 4 + 0] = v.x; regA[u * 4 + 1] = v.y; regA[u * 4 + 2] = v.z; regA[u * 4 + 3] = v.w;
    }
#pragma unroll
    for (int q = 0; q < 16; q++) {
        int j = tid + q * 256;
        int nn = j & 127, kk = j >> 7;
        regB[q] = W[(long long)kk * VVQ + n0 + nn];
    }

    int T = DDQ / 32;  // 16
    for (int t = 0; t < T; t++) {
#pragma unroll
        for (int u = 0; u < 16; u++) At[akb + u][am] = f2tf(regA[u]);
#pragma unroll
        for (int q = 0; q < 16; q++) {
            int j = tid + q * 256;
            int nn = j & 127, kk = j >> 7;
            Bt[kk][nn] = f2tf(regB[q]);
        }
        __syncthreads();
        if (t + 1 < T) {
            int k0 = (t + 1) * 32;
            const float* Ap = A + (long long)(m0 + am) * DDQ + k0 + akb;
#pragma unroll
            for (int u = 0; u < 4; u++) {
                float4 v = *(const float4*)(Ap + u * 4);
                regA[u * 4 + 0] = v.x; regA[u * 4 + 1] = v.y; regA[u * 4 + 2] = v.z; regA[u * 4 + 3] = v.w;
            }
#pragma unroll
            for (int q = 0; q < 16; q++) {
                int j = tid + q * 256;
                int nn = j & 127, kk = j >> 7;
                regB[q] = W[(long long)(k0 + kk) * VVQ + n0 + nn];
            }
        }
#pragma unroll
        for (int ks = 0; ks < 32; ks += 8) {
            unsigned af[4][4], bf[4][2];
#pragma unroll
            for (int mf = 0; mf < 4; mf++) {
                int mr = wm * 64 + mf * 16 + grp;
                af[mf][0] = At[ks + tig][mr];
                af[mf][1] = At[ks + tig][mr + 8];
                af[mf][2] = At[ks + tig + 4][mr];
                af[mf][3] = At[ks + tig + 4][mr + 8];
            }
#pragma unroll
            for (int nf = 0; nf < 4; nf++) {
                int nc = wn * 32 + nf * 8 + grp;
                bf[nf][0] = Bt[ks + tig][nc];
                bf[nf][1] = Bt[ks + tig + 4][nc];
            }
#pragma unroll
            for (int mf = 0; mf < 4; mf++)
#pragma unroll
                for (int nf = 0; nf < 4; nf++) mma8(acc[mf][nf], af[mf], bf[nf]);
        }
        __syncthreads();
    }

#pragma unroll
    for (int mf = 0; mf < 4; mf++)
#pragma unroll
        for (int nf = 0; nf < 4; nf++)
#pragma unroll
            for (int half = 0; half < 2; half++) {
                int m = m0 + wm * 64 + mf * 16 + grp + half * 8;
                int n = n0 + wn * 32 + nf * 8 + tig * 2;
                float v0 = acc[mf][nf][half * 2 + 0] + bias[n];
                float v1 = acc[mf][nf][half * 2 + 1] + bias[n + 1];
                *(float2*)&C[(long long)m * VVQ + n] = make_float2(v0, v1);
            }
}

// ---------------- embeddings ----------------
__global__ void embed_kernel(const int* __restrict__ tokens, const float* __restrict__ tok_emb,
                             const float* __restrict__ pos_emb, float* __restrict__ out, int Slen) {
    int b = blockIdx.y;
    __shared__ int pos[SSQ];
    if (threadIdx.x == 0) {
        int c = 0;
        for (int s = 0; s < Slen; s++) {
            int m = (tokens[b * Slen + s] != 0) ? 1 : 0;
            c += m;
            pos[s] = c * m;
        }
    }
    __syncthreads();
    int chunk = Slen / gridDim.x;
    int s0 = blockIdx.x * chunk;
    for (int idx = threadIdx.x; idx < chunk * DDQ; idx += blockDim.x) {
        int s = s0 + idx / DDQ;
        int d = idx % DDQ;
        int tk = tokens[b * Slen + s];
        out[((long long)b * Slen + s) * DDQ + d] =
            tok_emb[(long long)tk * DDQ + d] + pos_emb[(long long)pos[s] * DDQ + d];
    }
}

// ---------------- im2col, cheap (r, b) grid indexing ----------------
__global__ void im2col_enc_kernel(const float* __restrict__ x, const int* __restrict__ tokens,
                                  float* __restrict__ out) {
    int r = blockIdx.x;        // 0..3*DDQ-1, r = ic*3 + k
    int b = blockIdx.y;
    int s = threadIdx.x;       // 0..SSQ-1
    int ic = r / 3, k = r - ic * 3;
    int s2 = s + k - 1;
    float v = 0.f;
    if (s2 >= 0 && s2 < SSQ && tokens[b * SSQ + s2] != 0)
        v = x[((long long)b * DDQ + ic) * SSQ + s2];
    out[((long long)b * 3 * DDQ + r) * SSQ + s] = v;
}

__global__ void im2col_dec_kernel(const float* __restrict__ x, float* __restrict__ out) {
    int r = blockIdx.x;
    int b = blockIdx.y;
    int t = threadIdx.x;       // 0..TTQ-1
    int ic = r / 3, k = r - ic * 3;
    int t2 = t + k - 2;        // causal: pad K-1=2 left
    float v = (t2 >= 0) ? x[((long long)b * DDQ + ic) * TTQ + t2] : 0.f;
    out[((long long)b * 3 * DDQ + r) * TTQ + t] = v;
}

// ---------------- GLU (+ optional residual), float4 ----------------
__global__ void glu_res_kernel(const float* __restrict__ y, float* __restrict__ x,
                               int total4, int DS4, int apply_res) {
    int i = blockIdx.x * blockDim.x + threadIdx.x;
    if (i >= total4) return;
    int b = i / DS4;
    int rem = i - b * DS4;
    float4 a = ((const float4*)y)[(long long)b * 2 * DS4 + rem];
    float4 g = ((const float4*)y)[(long long)b * 2 * DS4 + DS4 + rem];
    float4 v;
    v.x = a.x / (1.f + expf(-g.x));
    v.y = a.y / (1.f + expf(-g.y));
    v.z = a.z / (1.f + expf(-g.z));
    v.w = a.w / (1.f + expf(-g.w));
    if (apply_res) {
        float4 xv = ((float4*)x)[i];
        v.x = (v.x + xv.x) * R2F; v.y = (v.y + xv.y) * R2F;
        v.z = (v.z + xv.z) * R2F; v.w = (v.w + xv.w) * R2F;
    }
    ((float4*)x)[i] = v;
}

// ---------------- decoder combine: x = ((c + att2^T)*R2 + x)*R2, (ch,b) grid ----
__global__ void dec_combine_kernel(float* __restrict__ x, const float* __restrict__ c,
                                   const float* __restrict__ att2) {
    int ch = blockIdx.x;
    int b = blockIdx.y;
    int t = threadIdx.x;       // 0..TTQ-1
    long long idx = ((long long)b * DDQ + ch) * TTQ + t;
    float cc = (c[idx] + att2[((long long)b * TTQ + t) * DDQ + ch]) * R2F;
    x[idx] = (cc + x[idx]) * R2F;
}

// ---------------- masked softmax over S ----------------
__global__ void softmax_mask_kernel(float* __restrict__ energy, const int* __restrict__ src) {
    int row = blockIdx.x;           // b*T + t
    int b = row / TTQ;
    float* e = energy + (long long)row * SSQ;
    int s = threadIdx.x;            // 256 = S
    float v = (src[b * SSQ + s] == 0) ? -INFINITY : e[s];
    __shared__ float red[SSQ];
    red[s] = v;
    __syncthreads();
    for (int off = 128; off > 0; off >>= 1) {
        if (s < off) red[s] = fmaxf(red[s], red[s + off]);
        __syncthreads();
    }
    float mx = red[0];
    __syncthreads();
    float ex = expf(v - mx);
    red[s] = ex;
    __syncthreads();
    for (int off = 128; off > 0; off >>= 1) {
        if (s < off) red[s] += red[s + off];
        __syncthreads();
    }
    e[s] = ex / red[0];
}

// ---------------- host side ----------------
static void gemm(const float* A, long long a_sm, long long a_sk, long long a_b,
                 const float* Bm, long long b_sk, long long b_sn, long long b_b,
                 float* C, long long c_row, long long c_b,
                 const float* bias, int bias_per_m,
                 int M, int N, int K, int nb,
                 int mode = 0, const int* tokens = nullptr,
                 const float* emb = nullptr, long long emb_b = 0, float* C2 = nullptr,
                 int splits = 1) {
    GemmP p;
    p.A = A; p.a_sm = a_sm; p.a_sk = a_sk; p.a_b = a_b;
    p.Bm = Bm; p.b_sk = b_sk; p.b_sn = b_sn; p.b_b = b_b;
    p.C = C; p.c_row = c_row; p.c_b = c_b;
    p.bias = bias; p.bias_per_m = bias_per_m;
    p.M = M; p.N = N; p.K = K; p.mode = mode;
    p.tokens = tokens; p.emb = emb; p.emb_b = emb_b; p.C2 = C2;
    dim3 grid(N / 64, M / 128, nb);
    if (splits == 3) tgemm_kernel<3><<<grid, 256>>>(p);
    else             tgemm_kernel<1><<<grid, 256>>>(p);
}

extern "C" void kernel_launch(void* const* d_in, const int* in_sizes, int n_in,
                              void* d_out, int out_size) {
    const int*   src        = (const int*)d_in[0];
    const int*   trg        = (const int*)d_in[1];
    const float* enc_tok    = (const float*)d_in[2];
    const float* enc_pos    = (const float*)d_in[3];
    const float* dec_tok    = (const float*)d_in[4];
    const float* dec_pos    = (const float*)d_in[5];
    const float* enc_in_w   = (const float*)d_in[6];
    const float* enc_in_b   = (const float*)d_in[7];
    const float* enc_conv_w = (const float*)d_in[8];
    const float* enc_conv_b = (const float*)d_in[9];
    const float* enc_out_w  = (const float*)d_in[10];
    const float* enc_out_b  = (const float*)d_in[11];
    const float* dec_in_w   = (const float*)d_in[12];
    const float* dec_in_b   = (const float*)d_in[13];
    const float* dec_conv_w = (const float*)d_in[14];
    const float* dec_conv_b = (const float*)d_in[15];
    const float* attn_in_w  = (const float*)d_in[16];
    const float* attn_in_b  = (const float*)d_in[17];
    const float* attn_out_w = (const float*)d_in[18];
    const float* attn_out_b = (const float*)d_in[19];
    const float* dec_out_w  = (const float*)d_in[20];
    const float* dec_out_b  = (const float*)d_in[21];
    const float* vocab_w    = (const float*)d_in[22];
    const float* vocab_b    = (const float*)d_in[23];
    float* logits = (float*)d_out;

    void* sp;
    cudaGetSymbolAddress(&sp, g_scratch);
    float* base = (float*)sp;
    float* enc_emb    = base;
    float* enc_x      = base + 2097152;
    float* im2col     = base + 4194304;
    float* ybuf       = base + 10485760;
    float* enc_conved = base + 14680064;
    float* enc_comb   = base + 16777216;
    float* dec_emb    = base + 18874368;
    float* dec_x      = base + 19922944;
    float* dec_c      = base + 20971520;
    float* qbuf       = base + 22020096;
    float* energy     = base + 23068672;
    float* att        = base + 23592960;
    float* att2       = base + 24641536;

    // ---- embeddings ----
    embed_kernel<<<dim3(4, BB), 256>>>(src, enc_tok, enc_pos, enc_emb, SSQ);
    embed_kernel<<<dim3(4, BB), 256>>>(trg, dec_tok, dec_pos, dec_emb, TTQ);

    // ---- encoder in-projection -> x[b][c][s]  [tf32] ----
    gemm(enc_in_w, 1, DDQ, 0,
         enc_emb, 1, DDQ, (long long)SSQ * DDQ,
         enc_x, SSQ, (long long)DDQ * SSQ,
         enc_in_b, 1, DDQ, SSQ, DDQ, BB);

    // ---- encoder conv stack  [tf32] ----
    for (int l = 0; l < LLQ; l++) {
        im2col_enc_kernel<<<dim3(3 * DDQ, BB), SSQ>>>(enc_x, src, im2col);
        gemm(enc_conv_w + (long long)l * 2 * DDQ * DDQ * 3, 3 * DDQ, 1, 0,
             im2col, SSQ, 1, (long long)3 * DDQ * SSQ,
             ybuf, SSQ, (long long)2 * DDQ * SSQ,
             enc_conv_b + l * 2 * DDQ, 1, 2 * DDQ, SSQ, 3 * DDQ, BB);
        int tot4 = BB * DDQ * SSQ / 4;
        glu_res_kernel<<<(tot4 + 255) / 256, 256>>>(ybuf, enc_x, tot4, DDQ * SSQ / 4, 1);
    }

    // ---- encoder out-projection (+pad mask, combined)  [tf32] ----
    gemm(enc_x, 1, SSQ, (long long)DDQ * SSQ,
         enc_out_w, DDQ, 1, 0,
         enc_conved, DDQ, (long long)SSQ * DDQ,
         enc_out_b, 0, SSQ, DDQ, DDQ, BB,
         1, src, enc_emb, (long long)SSQ * DDQ, enc_comb);

    // ---- decoder in-projection -> x[b][c][t]  [tf32] ----
    gemm(dec_in_w, 1, DDQ, 0,
         dec_emb, 1, DDQ, (long long)TTQ * DDQ,
         dec_x, TTQ, (long long)DDQ * TTQ,
         dec_in_b, 1, DDQ, TTQ, DDQ, BB);

    // ---- decoder layers ----
    for (int l = 0; l < LLQ; l++) {
        im2col_dec_kernel<<<dim3(3 * DDQ, BB), TTQ>>>(dec_x, im2col);
        gemm(dec_conv_w + (long long)l * 2 * DDQ * DDQ * 3, 3 * DDQ, 1, 0,
             im2col, TTQ, 1, (long long)3 * DDQ * TTQ,
             ybuf, TTQ, (long long)2 * DDQ * TTQ,
             dec_conv_b + l * 2 * DDQ, 1, 2 * DDQ, TTQ, 3 * DDQ, BB);
        int tot4 = BB * DDQ * TTQ / 4;
        glu_res_kernel<<<(tot4 + 255) / 256, 256>>>(ybuf, dec_c, tot4, DDQ * TTQ / 4, 0);

        // q = (c^T @ Wq + bq + emb) * R2   [tf32]
        gemm(dec_c, 1, TTQ, (long long)DDQ * TTQ,
             attn_in_w + (long long)l * DDQ * DDQ, DDQ, 1, 0,
             qbuf, DDQ, (long long)TTQ * DDQ,
             attn_in_b + l * DDQ, 0, TTQ, DDQ, DDQ, BB,
             2, nullptr, dec_emb, (long long)TTQ * DDQ, nullptr);

        // energy = q @ enc_conved^T   [tf32]
        gemm(qbuf, DDQ, 1, (long long)TTQ * DDQ,
             enc_conved, 1, DDQ, (long long)SSQ * DDQ,
             energy, SSQ, (long long)TTQ * SSQ,
             nullptr, 0, TTQ, SSQ, DDQ, BB);

        softmax_mask_kernel<<<BB * TTQ, SSQ>>>(energy, src);

        // att = attn @ enc_combined   [tf32]
        gemm(energy, SSQ, 1, (long long)TTQ * SSQ,
             enc_comb, DDQ, 1, (long long)SSQ * DDQ,
             att, DDQ, (long long)TTQ * DDQ,
             nullptr, 0, TTQ, DDQ, SSQ, BB);

        // att2 = att @ Wout + bout   [tf32]
        gemm(att, DDQ, 1, 0,
             attn_out_w + (long long)l * DDQ * DDQ, DDQ, 1, 0,
             att2, DDQ, 0,
             attn_out_b + l * DDQ, 0, BB * TTQ, DDQ, DDQ, 1);

        dec_combine_kernel<<<dim3(DDQ, BB), TTQ>>>(dec_x, dec_c, att2);
    }

    // ---- decoder out-projection -> [B,T,D] (reuse qbuf)  [tf32] ----
    gemm(dec_x, 1, TTQ, (long long)DDQ * TTQ,
         dec_out_w, DDQ, 1, 0,
         qbuf, DDQ, (long long)TTQ * DDQ,
         dec_out_b, 0, TTQ, DDQ, DDQ, BB);

    // ---- vocab projection -> logits [B*T, V] ----
    vgemm_kernel<<<dim3(VVQ / 128, (BB * TTQ) / 128), 256>>>(qbuf, vocab_w, vocab_b, logits);
}

// round 16
// speedup vs baseline: 1.1416x; 1.0017x over previous
#include <cuda_runtime.h>
#include <cuda_bf16.h>
#include <math.h>

#define BB 16
#define SSQ 256
#define TTQ 128
#define DDQ 512
#define VVQ 32000
#define LLQ 3
#define R2F 0.70710678118654752440f

// ---------------- scratch (single __device__ array, no allocs) ----------------
__device__ float g_scratch[25690112];

// ---------------- tensor-core batched GEMM (128x64 tile, 2 CTAs/SM) --------------
// SPLITS=3: bf16 split-pair planes; SPLITS=1: tf32 even/odd-k planes (2x mma8).
// glu=1: A rows remapped so acc[0]=a-half (oc), acc[1]=g-half (oc+DDQ);
//        epilogue computes GLU (+residual for mode 4) directly.
struct GemmP {
    const float* A; long long a_sm, a_sk, a_b;
    const float* Bm; long long b_sk, b_sn, b_b;
    float* C; long long c_row, c_b;
    const float* bias; int bias_per_m;
    int M, N, K, mode;  // 0 plain, 1 enc-out (+mask+combined), 2 (+emb)*R2, 3 glu, 4 glu+res*R2
    const int* tokens;
    const float* emb; long long emb_b;
    float* C2;
    int glu;
};

__device__ __forceinline__ unsigned f2tf(float x) {
    unsigned r;
    asm("cvt.rna.tf32.f32 %0, %1;" : "=r"(r) : "f"(x));
    return r;
}

__device__ __forceinline__ void cvt_pair(float x0, float x1, unsigned& hw, unsigned& lw) {
    __nv_bfloat162 h = __floats2bfloat162_rn(x0, x1);
    float2 hf = __bfloat1622float2(h);
    __nv_bfloat162 l = __floats2bfloat162_rn(x0 - hf.x, x1 - hf.y);
    hw = *reinterpret_cast<unsigned*>(&h);
    lw = *reinterpret_cast<unsigned*>(&l);
}

__device__ __forceinline__ void mma16(float* d, const unsigned* a, const unsigned* b) {
    asm volatile(
        "mma.sync.aligned.m16n8k16.row.col.f32.bf16.bf16.f32 "
        "{%0,%1,%2,%3}, {%4,%5,%6,%7}, {%8,%9}, {%0,%1,%2,%3};"
        : "+f"(d[0]), "+f"(d[1]), "+f"(d[2]), "+f"(d[3])
        : "r"(a[0]), "r"(a[1]), "r"(a[2]), "r"(a[3]), "r"(b[0]), "r"(b[1]));
}

__device__ __forceinline__ void mma8(float* d, const unsigned* a, const unsigned* b) {
    asm volatile(
        "mma.sync.aligned.m16n8k8.row.col.f32.tf32.tf32.f32 "
        "{%0,%1,%2,%3}, {%4,%5,%6,%7}, {%8,%9}, {%0,%1,%2,%3};"
        : "+f"(d[0]), "+f"(d[1]), "+f"(d[2]), "+f"(d[3])
        : "r"(a[0]), "r"(a[1]), "r"(a[2]), "r"(a[3]), "r"(b[0]), "r"(b[1]));
}

template <int SPLITS>
__device__ __forceinline__ void enc_pair(float x0, float x1, unsigned& hw, unsigned& lw) {
    if (SPLITS == 3) cvt_pair(x0, x1, hw, lw);
    else { hw = f2tf(x0); lw = f2tf(x1); }
}

// glu row remap: logical mm in [0,128) -> physical A row
__device__ __forceinline__ int glu_row(int m0, int mm) {
    return (m0 >> 1) + ((mm & 15) | ((mm >> 5) << 4)) + ((mm >> 4) & 1) * DDQ;
}

// ---- A tile: 128(m) x 32(k) into 16 regs ----
__device__ __forceinline__ void load_tileA(const GemmP& p, long long base, int m0, int k0,
                                           int tid, float* r) {
    if (p.a_sk == 1) {
        int mm = tid >> 1, kb = (tid & 1) << 4;
        int row = p.glu ? glu_row(m0, mm) : (m0 + mm);
        const float* q = p.A + base + (long long)row * p.a_sm + k0 + kb;
#pragma unroll
        for (int u = 0; u < 4; u++) {
            float4 v = *(const float4*)(q + u * 4);
            r[u * 4 + 0] = v.x; r[u * 4 + 1] = v.y; r[u * 4 + 2] = v.z; r[u * 4 + 3] = v.w;
        }
    } else {
#pragma unroll
        for (int q = 0; q < 8; q++) {
            int j = tid + q * 256;
            int mm = j & 127, k2 = j >> 7;
            int row = p.glu ? glu_row(m0, mm) : (m0 + mm);
            long long b2 = base + (long long)row * p.a_sm;
            r[q * 2]     = p.A[b2 + (long long)(k0 + 2 * k2) * p.a_sk];
            r[q * 2 + 1] = p.A[b2 + (long long)(k0 + 2 * k2 + 1) * p.a_sk];
        }
    }
}

template <int SPLITS>
__device__ __forceinline__ void sts_tileA(unsigned (*H)[136], unsigned (*L)[136],
                                          bool contig, int tid, const float* r) {
    if (contig) {
        int mm = tid >> 1, kb2 = (tid & 1) << 3;
#pragma unroll
        for (int u = 0; u < 8; u++)
            enc_pair<SPLITS>(r[u * 2], r[u * 2 + 1], H[kb2 + u][mm], L[kb2 + u][mm]);
    } else {
#pragma unroll
        for (int q = 0; q < 8; q++) {
            int j = tid + q * 256;
            int mm = j & 127, k2 = j >> 7;
            enc_pair<SPLITS>(r[q * 2], r[q * 2 + 1], H[k2][mm], L[k2][mm]);
        }
    }
}

// ---- B tile: 64(n) x 32(k) into 8 regs ----
__device__ __forceinline__ void load_tileB(const GemmP& p, long long base, int n0, int k0,
                                           int tid, float* r) {
    if (p.b_sk == 1) {
        int nn = tid >> 2, kb = (tid & 3) << 3;
        const float* q = p.Bm + base + (long long)(n0 + nn) * p.b_sn + k0 + kb;
#pragma unroll
        for (int u = 0; u < 2; u++) {
            float4 v = *(const float4*)(q + u * 4);
            r[u * 4 + 0] = v.x; r[u * 4 + 1] = v.y; r[u * 4 + 2] = v.z; r[u * 4 + 3] = v.w;
        }
    } else {
#pragma unroll
        for (int q = 0; q < 4; q++) {
            int j = tid + q * 256;
            int nn = j & 63, k2 = j >> 6;
            long long b2 = base + (long long)(n0 + nn) * p.b_sn;
            r[q * 2]     = p.Bm[b2 + (long long)(k0 + 2 * k2) * p.b_sk];
            r[q * 2 + 1] = p.Bm[b2 + (long long)(k0 + 2 * k2 + 1) * p.b_sk];
        }
    }
}

template <int SPLITS>
__device__ __forceinline__ void sts_tileB(unsigned (*H)[72], unsigned (*L)[72],
                                          bool contig, int tid, const float* r) {
    if (contig) {
        int nn = tid >> 2, kb2 = (tid & 3) << 2;
#pragma unroll
        for (int u = 0; u < 4; u++)
            enc_pair<SPLITS>(r[u * 2], r[u * 2 + 1], H[kb2 + u][nn], L[kb2 + u][nn]);
    } else {
#pragma unroll
        for (int q = 0; q < 4; q++) {
            int j = tid + q * 256;
            int nn = j & 63, k2 = j >> 6;
            enc_pair<SPLITS>(r[q * 2], r[q * 2 + 1], H[k2][nn], L[k2][nn]);
        }
    }
}

template <int SPLITS>
__global__ __launch_bounds__(256, 2) void tgemm_kernel(GemmP p) {
    __shared__ unsigned Ah[16][136], Al[16][136];
    __shared__ unsigned Bh[16][72], Bl[16][72];
    int bz = blockIdx.z;
    long long Abase = (long long)bz * p.a_b;
    long long Bbase = (long long)bz * p.b_b;
    int m0 = blockIdx.y * 128, n0 = blockIdx.x * 64;
    int tid = threadIdx.x;
    int warp = tid >> 5, lane = tid & 31;
    int wm = warp >> 1, wn = warp & 1;   // 4x2 warps; warp tile 32(m) x 32(n)
    int tig = lane & 3, grp = lane >> 2;
    bool acontig = (p.a_sk == 1);
    bool bcontig = (p.b_sk == 1);

    float acc[2][4][4];
#pragma unroll
    for (int i = 0; i < 2; i++)
#pragma unroll
        for (int j = 0; j < 4; j++)
#pragma unroll
            for (int r = 0; r < 4; r++) acc[i][j][r] = 0.f;

    float regA[16], regB[8];
    int T = p.K / 32;
    load_tileA(p, Abase, m0, 0, tid, regA);
    load_tileB(p, Bbase, n0, 0, tid, regB);

    for (int t = 0; t < T; t++) {
        sts_tileA<SPLITS>(Ah, Al, acontig, tid, regA);
        sts_tileB<SPLITS>(Bh, Bl, bcontig, tid, regB);
        __syncthreads();
        if (t + 1 < T) {
            load_tileA(p, Abase, m0, (t + 1) * 32, tid, regA);
            load_tileB(p, Bbase, n0, (t + 1) * 32, tid, regB);
        }
#pragma unroll
        for (int kc2 = 0; kc2 < 16; kc2 += 8) {
            unsigned ah[2][4], al[2][4], bh[4][2], bl[4][2];
#pragma unroll
            for (int mf = 0; mf < 2; mf++) {
                int mr = wm * 32 + mf * 16 + grp;
                ah[mf][0] = Ah[kc2 + tig][mr];
                ah[mf][1] = Ah[kc2 + tig][mr + 8];
                ah[mf][2] = Ah[kc2 + tig + 4][mr];
                ah[mf][3] = Ah[kc2 + tig + 4][mr + 8];
                al[mf][0] = Al[kc2 + tig][mr];
                al[mf][1] = Al[kc2 + tig][mr + 8];
                al[mf][2] = Al[kc2 + tig + 4][mr];
                al[mf][3] = Al[kc2 + tig + 4][mr + 8];
            }
#pragma unroll
            for (int nf = 0; nf < 4; nf++) {
                int nc = wn * 32 + nf * 8 + grp;
                bh[nf][0] = Bh[kc2 + tig][nc];
                bh[nf][1] = Bh[kc2 + tig + 4][nc];
                bl[nf][0] = Bl[kc2 + tig][nc];
                bl[nf][1] = Bl[kc2 + tig + 4][nc];
            }
#pragma unroll
            for (int mf = 0; mf < 2; mf++)
#pragma unroll
                for (int nf = 0; nf < 4; nf++) {
                    if (SPLITS == 3) {
                        mma16(acc[mf][nf], ah[mf], bh[nf]);
                        mma16(acc[mf][nf], ah[mf], bl[nf]);
                        mma16(acc[mf][nf], al[mf], bh[nf]);
                    } else {
                        mma8(acc[mf][nf], ah[mf], bh[nf]);  // even k
                        mma8(acc[mf][nf], al[mf], bl[nf]);  // odd k
                    }
                }
        }
        __syncthreads();
    }

    // ---- epilogue ----
    if (p.mode >= 3) {
        // GLU: acc[0]=a-half (oc), acc[1]=g-half (oc+DDQ); write 64 oc rows/block
#pragma unroll
        for (int nf = 0; nf < 4; nf++) {
#pragma unroll
            for (int half = 0; half < 2; half++) {
                int oc = (m0 >> 1) + wm * 16 + grp + half * 8;
                int n = n0 + wn * 32 + nf * 8 + tig * 2;
                float ba = p.bias[oc], bg = p.bias[DDQ + oc];
                float a0 = acc[0][nf][half * 2 + 0] + ba;
                float a1 = acc[0][nf][half * 2 + 1] + ba;
                float g0 = acc[1][nf][half * 2 + 0] + bg;
                float g1 = acc[1][nf][half * 2 + 1] + bg;
                float v0 = a0 / (1.f + expf(-g0));
                float v1 = a1 / (1.f + expf(-g1));
                long long cidx = (long long)bz * p.c_b + (long long)oc * p.c_row + n;
                if (p.mode == 4) {
                    float2 r = *(float2*)&p.C[cidx];
                    v0 = (v0 + r.x) * R2F;
                    v1 = (v1 + r.y) * R2F;
                }
                *(float2*)&p.C[cidx] = make_float2(v0, v1);
            }
        }
        return;
    }
#pragma unroll
    for (int mf = 0; mf < 2; mf++) {
#pragma unroll
        for (int nf = 0; nf < 4; nf++) {
#pragma unroll
            for (int half = 0; half < 2; half++) {
                int m = m0 + wm * 32 + mf * 16 + grp + half * 8;
                int n = n0 + wn * 32 + nf * 8 + tig * 2;
                float v0 = acc[mf][nf][half * 2 + 0];
                float v1 = acc[mf][nf][half * 2 + 1];
                if (p.bias) {
                    if (p.bias_per_m) { float bm = p.bias[m]; v0 += bm; v1 += bm; }
                    else { v0 += p.bias[n]; v1 += p.bias[n + 1]; }
                }
                long long cidx = (long long)bz * p.c_b + (long long)m * p.c_row + n;
                if (p.mode == 0) {
                    *(float2*)&p.C[cidx] = make_float2(v0, v1);
                } else if (p.mode == 1) {
                    int tok = p.tokens[bz * SSQ + m];
                    if (tok == 0) { v0 = 0.f; v1 = 0.f; }
                    *(float2*)&p.C[cidx] = make_float2(v0, v1);
                    float2 e = *(const float2*)&p.emb[(long long)bz * p.emb_b + (long long)m * p.N + n];
                    *(float2*)&p.C2[cidx] = make_float2((v0 + e.x) * R2F, (v1 + e.y) * R2F);
                } else {
                    float2 e = *(const float2*)&p.emb[(long long)bz * p.emb_b + (long long)m * p.N + n];
                    *(float2*)&p.C[cidx] = make_float2((v0 + e.x) * R2F, (v1 + e.y) * R2F);
                }
            }
        }
    }
}

// ---------------- vocab GEMM: 1x tf32, pipelined (R7-proven) ----------------
__global__ __launch_bounds__(256) void vgemm_kernel(const float* __restrict__ A,
                                                    const float* __restrict__ W,
                                                    const float* __restrict__ bias,
                                                    float* __restrict__ C) {
    __shared__ unsigned At[32][136], Bt[32][136];
    int m0 = blockIdx.y * 128, n0 = blockIdx.x * 128;
    int tid = threadIdx.x;
    int warp = tid >> 5, lane = tid & 31;
    int wm = warp >> 2, wn = warp & 3;
    int tig = lane & 3, grp = lane >> 2;

    float acc[4][4][4];
#pragma unroll
    for (int i = 0; i < 4; i++)
#pragma unroll
        for (int j = 0; j < 4; j++)
#pragma unroll
            for (int r = 0; r < 4; r++) acc[i][j][r] = 0.f;

    int am = tid >> 1, akb = (tid & 1) << 4;
    float regA[16], regB[16];

    const float* Ap0 = A + (long long)(m0 + am) * DDQ + akb;
#pragma unroll
    for (int u = 0; u < 4; u++) {
        float4 v = *(const float4*)(Ap0 + u * 4);
        regA[u * 4 + 0] = v.x; regA[u * 4 + 1] = v.y; regA[u * 4 + 2] = v.z; regA[u * 4 + 3] = v.w;
    }
#pragma unroll
    for (int q = 0; q < 16; q++) {
        int j = tid + q * 256;
        int nn = j & 127, kk = j >> 7;
        regB[q] = W[(long long)kk * VVQ + n0 + nn];
    }

    int T = DDQ / 32;  // 16
    for (int t = 0; t < T; t++) {
#pragma unroll
        for (int u = 0; u < 16; u++) At[akb + u][am] = f2tf(regA[u]);
#pragma unroll
        for (int q = 0; q < 16; q++) {
            int j = tid + q * 256;
            int nn = j & 127, kk = j >> 7;
            Bt[kk][nn] = f2tf(regB[q]);
        }
        __syncthreads();
        if (t + 1 < T) {
            int k0 = (t + 1) * 32;
            const float* Ap = A + (long long)(m0 + am) * DDQ + k0 + akb;
#pragma unroll
            for (int u = 0; u < 4; u++) {
                float4 v = *(const float4*)(Ap + u * 4);
                regA[u * 4 + 0] = v.x; regA[u * 4 + 1] = v.y; regA[u * 4 + 2] = v.z; regA[u * 4 + 3] = v.w;
            }
#pragma unroll
            for (int q = 0; q < 16; q++) {
                int j = tid + q * 256;
                int nn = j & 127, kk = j >> 7;
                regB[q] = W[(long long)(k0 + kk) * VVQ + n0 + nn];
            }
        }
#pragma unroll
        for (int ks = 0; ks < 32; ks += 8) {
            unsigned af[4][4], bf[4][2];
#pragma unroll
            for (int mf = 0; mf < 4; mf++) {
                int mr = wm * 64 + mf * 16 + grp;
                af[mf][0] = At[ks + tig][mr];
                af[mf][1] = At[ks + tig][mr + 8];
                af[mf][2] = At[ks + tig + 4][mr];
                af[mf][3] = At[ks + tig + 4][mr + 8];
            }
#pragma unroll
            for (int nf = 0; nf < 4; nf++) {
                int nc = wn * 32 + nf * 8 + grp;
                bf[nf][0] = Bt[ks + tig][nc];
                bf[nf][1] = Bt[ks + tig + 4][nc];
            }
#pragma unroll
            for (int mf = 0; mf < 4; mf++)
#pragma unroll
                for (int nf = 0; nf < 4; nf++) mma8(acc[mf][nf], af[mf], bf[nf]);
        }
        __syncthreads();
    }

#pragma unroll
    for (int mf = 0; mf < 4; mf++)
#pragma unroll
        for (int nf = 0; nf < 4; nf++)
#pragma unroll
            for (int half = 0; half < 2; half++) {
                int m = m0 + wm * 64 + mf * 16 + grp + half * 8;
                int n = n0 + wn * 32 + nf * 8 + tig * 2;
                float v0 = acc[mf][nf][half * 2 + 0] + bias[n];
                float v1 = acc[mf][nf][half * 2 + 1] + bias[n + 1];
                *(float2*)&C[(long long)m * VVQ + n] = make_float2(v0, v1);
            }
}

// ---------------- embeddings ----------------
__global__ void embed_kernel(const int* __restrict__ tokens, const float* __restrict__ tok_emb,
                             const float* __restrict__ pos_emb, float* __restrict__ out, int Slen) {
    int b = blockIdx.y;
    __shared__ int pos[SSQ];
    if (threadIdx.x == 0) {
        int c = 0;
        for (int s = 0; s < Slen; s++) {
            int m = (tokens[b * Slen + s] != 0) ? 1 : 0;
            c += m;
            pos[s] = c * m;
        }
    }
    __syncthreads();
    int chunk = Slen / gridDim.x;
    int s0 = blockIdx.x * chunk;
    for (int idx = threadIdx.x; idx < chunk * DDQ; idx += blockDim.x) {
        int s = s0 + idx / DDQ;
        int d = idx % DDQ;
        int tk = tokens[b * Slen + s];
        out[((long long)b * Slen + s) * DDQ + d] =
            tok_emb[(long long)tk * DDQ + d] + pos_emb[(long long)pos[s] * DDQ + d];
    }
}

// ---------------- im2col, cheap (r, b) grid indexing ----------------
__global__ void im2col_enc_kernel(const float* __restrict__ x, const int* __restrict__ tokens,
                                  float* __restrict__ out) {
    int r = blockIdx.x;        // r = ic*3 + k
    int b = blockIdx.y;
    int s = threadIdx.x;
    int ic = r / 3, k = r - ic * 3;
    int s2 = s + k - 1;
    float v = 0.f;
    if (s2 >= 0 && s2 < SSQ && tokens[b * SSQ + s2] != 0)
        v = x[((long long)b * DDQ + ic) * SSQ + s2];
    out[((long long)b * 3 * DDQ + r) * SSQ + s] = v;
}

__global__ void im2col_dec_kernel(const float* __restrict__ x, float* __restrict__ out) {
    int r = blockIdx.x;
    int b = blockIdx.y;
    int t = threadIdx.x;
    int ic = r / 3, k = r - ic * 3;
    int t2 = t + k - 2;
    float v = (t2 >= 0) ? x[((long long)b * DDQ + ic) * TTQ + t2] : 0.f;
    out[((long long)b * 3 * DDQ + r) * TTQ + t] = v;
}

// ---------------- decoder combine: x = ((c + att2^T)*R2 + x)*R2, (ch,b) grid ----
__global__ void dec_combine_kernel(float* __restrict__ x, const float* __restrict__ c,
                                   const float* __restrict__ att2) {
    int ch = blockIdx.x;
    int b = blockIdx.y;
    int t = threadIdx.x;
    long long idx = ((long long)b * DDQ + ch) * TTQ + t;
    float cc = (c[idx] + att2[((long long)b * TTQ + t) * DDQ + ch]) * R2F;
    x[idx] = (cc + x[idx]) * R2F;
}

// ---------------- masked softmax over S ----------------
__global__ void softmax_mask_kernel(float* __restrict__ energy, const int* __restrict__ src) {
    int row = blockIdx.x;
    int b = row / TTQ;
    float* e = energy + (long long)row * SSQ;
    int s = threadIdx.x;
    float v = (src[b * SSQ + s] == 0) ? -INFINITY : e[s];
    __shared__ float red[SSQ];
    red[s] = v;
    __syncthreads();
    for (int off = 128; off > 0; off >>= 1) {
        if (s < off) red[s] = fmaxf(red[s], red[s + off]);
        __syncthreads();
    }
    float mx = red[0];
    __syncthreads();
    float ex = expf(v - mx);
    red[s] = ex;
    __syncthreads();
    for (int off = 128; off > 0; off >>= 1) {
        if (s < off) red[s] += red[s + off];
        __syncthreads();
    }
    e[s] = ex / red[0];
}

// ---------------- host side ----------------
static void gemm(const float* A, long long a_sm, long long a_sk, long long a_b,
                 const float* Bm, long long b_sk, long long b_sn, long long b_b,
                 float* C, long long c_row, long long c_b,
                 const float* bias, int bias_per_m,
                 int M, int N, int K, int nb,
                 int mode = 0, const int* tokens = nullptr,
                 const float* emb = nullptr, long long emb_b = 0, float* C2 = nullptr,
                 int splits = 1, int glu = 0) {
    GemmP p;
    p.A = A; p.a_sm = a_sm; p.a_sk = a_sk; p.a_b = a_b;
    p.Bm = Bm; p.b_sk = b_sk; p.b_sn = b_sn; p.b_b = b_b;
    p.C = C; p.c_row = c_row; p.c_b = c_b;
    p.bias = bias; p.bias_per_m = bias_per_m;
    p.M = M; p.N = N; p.K = K; p.mode = mode;
    p.tokens = tokens; p.emb = emb; p.emb_b = emb_b; p.C2 = C2;
    p.glu = glu;
    int gy = glu ? (M / 2) / 64 : M / 128;  // glu: 64 oc per block (128 logical rows)
    dim3 grid(N / 64, gy, nb);
    if (splits == 3) tgemm_kernel<3><<<grid, 256>>>(p);
    else             tgemm_kernel<1><<<grid, 256>>>(p);
}

extern "C" void kernel_launch(void* const* d_in, const int* in_sizes, int n_in,
                              void* d_out, int out_size) {
    const int*   src        = (const int*)d_in[0];
    const int*   trg        = (const int*)d_in[1];
    const float* enc_tok    = (const float*)d_in[2];
    const float* enc_pos    = (const float*)d_in[3];
    const float* dec_tok    = (const float*)d_in[4];
    const float* dec_pos    = (const float*)d_in[5];
    const float* enc_in_w   = (const float*)d_in[6];
    const float* enc_in_b   = (const float*)d_in[7];
    const float* enc_conv_w = (const float*)d_in[8];
    const float* enc_conv_b = (const float*)d_in[9];
    const float* enc_out_w  = (const float*)d_in[10];
    const float* enc_out_b  = (const float*)d_in[11];
    const float* dec_in_w   = (const float*)d_in[12];
    const float* dec_in_b   = (const float*)d_in[13];
    const float* dec_conv_w = (const float*)d_in[14];
    const float* dec_conv_b = (const float*)d_in[15];
    const float* attn_in_w  = (const float*)d_in[16];
    const float* attn_in_b  = (const float*)d_in[17];
    const float* attn_out_w = (const float*)d_in[18];
    const float* attn_out_b = (const float*)d_in[19];
    const float* dec_out_w  = (const float*)d_in[20];
    const float* dec_out_b  = (const float*)d_in[21];
    const float* vocab_w    = (const float*)d_in[22];
    const float* vocab_b    = (const float*)d_in[23];
    float* logits = (float*)d_out;

    void* sp;
    cudaGetSymbolAddress(&sp, g_scratch);
    float* base = (float*)sp;
    float* enc_emb    = base;
    float* enc_x      = base + 2097152;
    float* im2col     = base + 4194304;
    float* enc_conved = base + 14680064;
    float* enc_comb   = base + 16777216;
    float* dec_emb    = base + 18874368;
    float* dec_x      = base + 19922944;
    float* dec_c      = base + 20971520;
    float* qbuf       = base + 22020096;
    float* energy     = base + 23068672;
    float* att        = base + 23592960;
    float* att2       = base + 24641536;

    // ---- embeddings ----
    embed_kernel<<<dim3(4, BB), 256>>>(src, enc_tok, enc_pos, enc_emb, SSQ);
    embed_kernel<<<dim3(4, BB), 256>>>(trg, dec_tok, dec_pos, dec_emb, TTQ);

    // ---- encoder in-projection -> x[b][c][s] ----
    gemm(enc_in_w, 1, DDQ, 0,
         enc_emb, 1, DDQ, (long long)SSQ * DDQ,
         enc_x, SSQ, (long long)DDQ * SSQ,
         enc_in_b, 1, DDQ, SSQ, DDQ, BB);

    // ---- encoder conv stack (GLU+res fused into GEMM epilogue) ----
    for (int l = 0; l < LLQ; l++) {
        im2col_enc_kernel<<<dim3(3 * DDQ, BB), SSQ>>>(enc_x, src, im2col);
        gemm(enc_conv_w + (long long)l * 2 * DDQ * DDQ * 3, 3 * DDQ, 1, 0,
             im2col, SSQ, 1, (long long)3 * DDQ * SSQ,
             enc_x, SSQ, (long long)DDQ * SSQ,
             enc_conv_b + l * 2 * DDQ, 1, 2 * DDQ, SSQ, 3 * DDQ, BB,
             4, nullptr, nullptr, 0, nullptr, 1, 1);
    }

    // ---- encoder out-projection (+pad mask, combined) ----
    gemm(enc_x, 1, SSQ, (long long)DDQ * SSQ,
         enc_out_w, DDQ, 1, 0,
         enc_conved, DDQ, (long long)SSQ * DDQ,
         enc_out_b, 0, SSQ, DDQ, DDQ, BB,
         1, src, enc_emb, (long long)SSQ * DDQ, enc_comb);

    // ---- decoder in-projection -> x[b][c][t] ----
    gemm(dec_in_w, 1, DDQ, 0,
         dec_emb, 1, DDQ, (long long)TTQ * DDQ,
         dec_x, TTQ, (long long)DDQ * TTQ,
         dec_in_b, 1, DDQ, TTQ, DDQ, BB);

    // ---- decoder layers ----
    for (int l = 0; l < LLQ; l++) {
        im2col_dec_kernel<<<dim3(3 * DDQ, BB), TTQ>>>(dec_x, im2col);
        gemm(dec_conv_w + (long long)l * 2 * DDQ * DDQ * 3, 3 * DDQ, 1, 0,
             im2col, TTQ, 1, (long long)3 * DDQ * TTQ,
             dec_c, TTQ, (long long)DDQ * TTQ,
             dec_conv_b + l * 2 * DDQ, 1, 2 * DDQ, TTQ, 3 * DDQ, BB,
             3, nullptr, nullptr, 0, nullptr, 1, 1);

        // q = (c^T @ Wq + bq + emb) * R2
        gemm(dec_c, 1, TTQ, (long long)DDQ * TTQ,
             attn_in_w + (long long)l * DDQ * DDQ, DDQ, 1, 0,
             qbuf, DDQ, (long long)TTQ * DDQ,
             attn_in_b + l * DDQ, 0, TTQ, DDQ, DDQ, BB,
             2, nullptr, dec_emb, (long long)TTQ * DDQ, nullptr);

        // energy = q @ enc_conved^T
        gemm(qbuf, DDQ, 1, (long long)TTQ * DDQ,
             enc_conved, 1, DDQ, (long long)SSQ * DDQ,
             energy, SSQ, (long long)TTQ * SSQ,
             nullptr, 0, TTQ, SSQ, DDQ, BB);

        softmax_mask_kernel<<<BB * TTQ, SSQ>>>(energy, src);

        // att = attn @ enc_combined
        gemm(energy, SSQ, 1, (long long)TTQ * SSQ,
             enc_comb, DDQ, 1, (long long)SSQ * DDQ,
             att, DDQ, (long long)TTQ * DDQ,
             nullptr, 0, TTQ, DDQ, SSQ, BB);

        // att2 = att @ Wout + bout
        gemm(att, DDQ, 1, 0,
             attn_out_w + (long long)l * DDQ * DDQ, DDQ, 1, 0,
             att2, DDQ, 0,
             attn_out_b + l * DDQ, 0, BB * TTQ, DDQ, DDQ, 1);

        dec_combine_kernel<<<dim3(DDQ, BB), TTQ>>>(dec_x, dec_c, att2);
    }

    // ---- decoder out-projection -> [B,T,D] (reuse qbuf) ----
    gemm(dec_x, 1, TTQ, (long long)DDQ * TTQ,
         dec_out_w, DDQ, 1, 0,
         qbuf, DDQ, (long long)TTQ * DDQ,
         dec_out_b, 0, TTQ, DDQ, DDQ, BB);

    // ---- vocab projection -> logits [B*T, V] ----
    vgemm_kernel<<<dim3(VVQ / 128, (BB * TTQ) / 128), 256>>>(qbuf, vocab_w, vocab_b, logits);
}